// round 2
// baseline (speedup 1.0000x reference)
#include <cuda_runtime.h>
#include <cstdint>

// ============================================================================
// LinkPredictor on GB300 via mma.sync tf32 (tcgen05 unavailable: ptxas target
// is sm_103 without the 'a' feature set).
//   layer1: A[128,512] (edge features) @ W1[512,128] -> C1 (regs, fp32)
//   layer2: relu(C1+b1) @ W2[128,64]                 -> C2 (regs, fp32)
//   layer3: relu(C2+b2) . W3 + b3                    -> out[E]
// ============================================================================

#define TE 128               // edges per CTA

// ---- prep scratch: tf32-converted, pair-interleaved weights ----
__device__ __align__(16) float2 g_W1p[512 * 64];   // [k][q], {n_q, n_q+32}, n_q=(q&31)+(q>>5)*64
__device__ __align__(16) float2 g_W2p[128 * 32];   // [k][q], {n_q, n_q+16}, n_q=(q&15)+(q>>4)*32

// ---- smem geometry (word strides chosen for conflict-free fragments) ----
#define S_STR  132           // fp32 words/row: 132 mod 32 = 4  (A-frag 8 rows x 4 cols OK)
#define PQ_STR 36            // 36 mod 32 = 4
#define B1_STR 136           // words/row (64 float2 + pad): 136 mod 32 = 8 (B-frag LDS.64 OK)
#define W2_STR 72            // words/row (32 float2 + pad): 72 mod 32 = 8

#define SM_S    0            // [128][132] f32 = 67584
#define SM_D    67584        // [128][132] f32 = 67584
#define SM_P    135168       // [128][36]  tf32 = 18432
#define SM_Q    153600       // [128][36]  tf32 = 18432
#define SM_B1   172032       // 2 x 32 rows x 136 words = 2 x 17408
#define B1_BUF  17408
#define SM_SMALL 206848      // b1[128] | b2[64] | w3[64] | b3 | flag
#define SMEM_TOTAL 207936
#define SM_A2   SM_S         // layer2 A: [128][132] tf32 (reuses S)
#define SM_W2   SM_D         // layer2 B: 128 rows x 72 words = 36864 (reuses D)
#define SM_R    SM_P         // reduction buffer [2][128] f32

__device__ __forceinline__ uint32_t smem_u32(const void* p) {
    uint32_t a;
    asm("{ .reg .u64 t; cvta.to.shared.u64 t, %1; cvt.u32.u64 %0, t; }" : "=r"(a) : "l"(p));
    return a;
}
__device__ __forceinline__ float f2tf(float f) {
    uint32_t r; asm("cvt.rna.tf32.f32 %0, %1;" : "=r"(r) : "f"(f));
    return __uint_as_float(r);
}
__device__ __forceinline__ uint32_t f2tfu(float f) {
    uint32_t r; asm("cvt.rna.tf32.f32 %0, %1;" : "=r"(r) : "f"(f));
    return r;
}
__device__ __forceinline__ void cp16(uint32_t d, const void* s) {
    asm volatile("cp.async.ca.shared.global [%0], [%1], 16;" :: "r"(d), "l"(s) : "memory");
}
#define CP_COMMIT() asm volatile("cp.async.commit_group;" ::: "memory")
#define CP_WAIT0()  asm volatile("cp.async.wait_group 0;"  ::: "memory")

// m16n8k8 tf32 HMMA, accumulate in place
#define MMA(c, a, b)                                                           \
    asm volatile("mma.sync.aligned.m16n8k8.row.col.f32.tf32.tf32.f32 "         \
                 "{%0,%1,%2,%3}, {%4,%5,%6,%7}, {%8,%9}, {%0,%1,%2,%3};"       \
                 : "+f"((c)[0]), "+f"((c)[1]), "+f"((c)[2]), "+f"((c)[3])      \
                 : "r"((a)[0]), "r"((a)[1]), "r"((a)[2]), "r"((a)[3]),         \
                   "r"((b)[0]), "r"((b)[1]))

// ---------------------------------------------------------------------------
// prep: W1/W2 -> tf32, pair-interleaved
// ---------------------------------------------------------------------------
__global__ void prep_weights(const float* __restrict__ W1, const float* __restrict__ W2) {
    int i = blockIdx.x * blockDim.x + threadIdx.x;
    if (i < 512 * 64) {
        int k = i >> 6, q = i & 63;
        int n = (q & 31) + ((q >> 5) << 6);
        float2 v;
        v.x = f2tf(W1[k * 128 + n]);
        v.y = f2tf(W1[k * 128 + n + 32]);
        g_W1p[i] = v;
    } else {
        int j = i - 512 * 64;
        if (j < 128 * 32) {
            int k = j >> 5, q = j & 31;
            int n = (q & 15) + ((q >> 4) << 5);
            float2 v;
            v.x = f2tf(W2[k * 64 + n]);
            v.y = f2tf(W2[k * 64 + n + 16]);
            g_W2p[j] = v;
        }
    }
}

// ---------------------------------------------------------------------------
// layer-1 chunk consumer (K=32): warp tile 2 m-tiles x 8 n-tiles
// ---------------------------------------------------------------------------
template<int ASTR, bool CVT>
__device__ __forceinline__ void l1_chunk(const float* __restrict__ Ab,
                                         const char* __restrict__ Bb,
                                         float (&c1)[2][8][4],
                                         int mi, int ni, int t4, int cl)
{
    #pragma unroll
    for (int ks = 0; ks < 4; ks++) {
        uint32_t a[2][4];
        #pragma unroll
        for (int mt = 0; mt < 2; mt++) {
            const float* ap = Ab + (mi * 32 + mt * 16 + t4) * ASTR + ks * 8 + cl;
            float x0 = ap[0], x2 = ap[4];
            float x1 = ap[8 * ASTR], x3 = ap[8 * ASTR + 4];
            if (CVT) {
                a[mt][0] = f2tfu(x0); a[mt][1] = f2tfu(x1);
                a[mt][2] = f2tfu(x2); a[mt][3] = f2tfu(x3);
            } else {
                a[mt][0] = __float_as_uint(x0); a[mt][1] = __float_as_uint(x1);
                a[mt][2] = __float_as_uint(x2); a[mt][3] = __float_as_uint(x3);
            }
        }
        uint32_t b[8][2];
        #pragma unroll
        for (int np = 0; np < 4; np++) {
            int q = ni * 32 + np * 8 + t4;
            const char* bp = Bb + ((ks * 8 + cl) * B1_STR + q * 2) * 4;
            float2 p0 = *(const float2*)bp;
            float2 p1 = *(const float2*)(bp + 4 * B1_STR * 4);
            b[np][0]     = __float_as_uint(p0.x);
            b[np + 4][0] = __float_as_uint(p0.y);
            b[np][1]     = __float_as_uint(p1.x);
            b[np + 4][1] = __float_as_uint(p1.y);
        }
        #pragma unroll
        for (int mt = 0; mt < 2; mt++)
            #pragma unroll
            for (int nt = 0; nt < 8; nt++)
                MMA(c1[mt][nt], a[mt], b[nt]);
    }
}

// ---------------------------------------------------------------------------
__global__ void __launch_bounds__(256, 1)
lp_main(const float* __restrict__ z,
        const void*  __restrict__ eiv,
        const float* __restrict__ b1,
        const float* __restrict__ b2,
        const float* __restrict__ W3,
        const float* __restrict__ b3,
        float* __restrict__ out,
        int n_edges)
{
    extern __shared__ char smem[];
    float* sm = (float*)smem;
    const uint32_t sbase = smem_u32(smem);
    const int tid  = threadIdx.x;
    const int lane = tid & 31;
    const int wid  = tid >> 5;
    const int mi   = wid >> 1;      // m-slab 0..3 (32 rows)
    const int ni   = wid & 1;       // n-half 0..1 (64 cols layer1, 32 layer2)
    const int t4   = lane >> 2;
    const int cl   = lane & 3;
    const int tile_base = blockIdx.x * TE;

    float* b1s = sm + (SM_SMALL >> 2);
    float* b2s = b1s + 128;
    float* w3s = b2s + 64;
    float* b3s = w3s + 64;
    int*   flg = (int*)(b3s + 1);

    // ---- smalls + edge-index dtype detection ----
    if (tid < 128) b1s[tid] = b1[tid];
    if (tid < 64) { b2s[tid] = b2[tid]; w3s[tid] = W3[tid]; }
    if (tid == 0) {
        b3s[0] = b3[0];
        const unsigned* p = (const unsigned*)eiv;
        unsigned orv = 0;
        #pragma unroll
        for (int i = 0; i < 16; i++) orv |= p[2 * i + 1];
        flg[0] = (orv == 0) ? 1 : 0;     // 1 => int64 indices
    }

    // ---- stage B1 chunk 0 ----
    {
        #pragma unroll
        for (int r = 0; r < 4; r++) {
            int q = tid + 256 * r;
            int row = q >> 5, seg = q & 31;
            cp16(sbase + SM_B1 + row * (B1_STR * 4) + seg * 16,
                 (const char*)(g_W1p + row * 64) + seg * 16);
        }
        CP_COMMIT();
    }
    __syncthreads();   // flag visible

    // ---- gather: 2 threads/edge, 64 floats each of src and dst ----
    {
        const int le = tid >> 1, half = tid & 1;
        const long long e = (long long)tile_base + le;
        float4* Sp = (float4*)(sm + le * S_STR + half * 64);
        float4* Dp = (float4*)(sm + (SM_D >> 2) + le * S_STR + half * 64);
        if (e < n_edges) {
            long long si, di;
            if (flg[0]) {
                const long long* e64 = (const long long*)eiv;
                si = e64[e]; di = e64[(long long)n_edges + e];
            } else {
                const int* e32 = (const int*)eiv;
                si = e32[e]; di = e32[n_edges + e];
            }
            const float4* ps = (const float4*)(z + si * 128) + half * 16;
            const float4* pd = (const float4*)(z + di * 128) + half * 16;
            #pragma unroll
            for (int i = 0; i < 16; i++) { Sp[i] = ps[i]; Dp[i] = pd[i]; }
        } else {
            float4 zr = make_float4(0.f, 0.f, 0.f, 0.f);
            #pragma unroll
            for (int i = 0; i < 16; i++) { Sp[i] = zr; Dp[i] = zr; }
        }
    }

    float c1[2][8][4];
    #pragma unroll
    for (int mt = 0; mt < 2; mt++)
        #pragma unroll
        for (int nt = 0; nt < 8; nt++)
            #pragma unroll
            for (int v = 0; v < 4; v++) c1[mt][nt][v] = 0.f;

    // ======================= layer 1: 16 chunks of K=32 ======================
    #pragma unroll 1
    for (int c = 0; c < 16; c++) {
        const int j = c >> 2, fb = c & 3;

        CP_WAIT0();
        __syncthreads();   // chunk c staged; all warps done with previous buffers

        if (c + 1 < 16) {  // prefetch next chunk into other buffer
            const int jn = (c + 1) >> 2, fbn = (c + 1) & 3;
            const int kc = fbn * 128 + jn * 32;
            const int buf = (c + 1) & 1;
            #pragma unroll
            for (int r = 0; r < 4; r++) {
                int q = tid + 256 * r;
                int row = q >> 5, seg = q & 31;
                cp16(sbase + SM_B1 + buf * B1_BUF + row * (B1_STR * 4) + seg * 16,
                     (const char*)(g_W1p + (kc + row) * 64) + seg * 16);
            }
            CP_COMMIT();
        }

        if (fb == 2) {
            // build P = s*d, Q = |s-d| for column block j (fp32 math, tf32 store)
            const int row = tid >> 1, half = tid & 1;
            const float4* Sr = (const float4*)(sm + row * S_STR + j * 32 + half * 16);
            const float4* Dr = (const float4*)(sm + (SM_D >> 2) + row * S_STR + j * 32 + half * 16);
            float4* Pr = (float4*)(sm + (SM_P >> 2) + row * PQ_STR + half * 16);
            float4* Qr = (float4*)(sm + (SM_Q >> 2) + row * PQ_STR + half * 16);
            #pragma unroll
            for (int i = 0; i < 4; i++) {
                float4 s4 = Sr[i], d4 = Dr[i];
                Pr[i] = make_float4(f2tf(s4.x * d4.x), f2tf(s4.y * d4.y),
                                    f2tf(s4.z * d4.z), f2tf(s4.w * d4.w));
                Qr[i] = make_float4(f2tf(fabsf(s4.x - d4.x)), f2tf(fabsf(s4.y - d4.y)),
                                    f2tf(fabsf(s4.z - d4.z)), f2tf(fabsf(s4.w - d4.w)));
            }
            __syncthreads();
        }

        const char* Bb = smem + SM_B1 + (c & 1) * B1_BUF;
        if      (fb == 0) l1_chunk<S_STR,  true >(sm + j * 32,                Bb, c1, mi, ni, t4, cl);
        else if (fb == 1) l1_chunk<S_STR,  true >(sm + (SM_D >> 2) + j * 32,  Bb, c1, mi, ni, t4, cl);
        else if (fb == 2) l1_chunk<PQ_STR, false>(sm + (SM_P >> 2),           Bb, c1, mi, ni, t4, cl);
        else              l1_chunk<PQ_STR, false>(sm + (SM_Q >> 2),           Bb, c1, mi, ni, t4, cl);
    }

    // ---- stage W2p (overlaps epilogue-1) ----
    {
        #pragma unroll
        for (int r = 0; r < 8; r++) {
            int q = tid + 256 * r;
            int row = q >> 4, seg = q & 15;
            cp16(sbase + SM_W2 + row * (W2_STR * 4) + seg * 16,
                 (const char*)(g_W2p + row * 32) + seg * 16);
        }
        CP_COMMIT();
    }

    // ---- epilogue 1: A2 = tf32(relu(C1 + b1)), into SM_S region ----
    // (safe: chunk 15 reads only Q and B1; warps are past the iter-15 barrier)
    #pragma unroll
    for (int mt = 0; mt < 2; mt++) {
        const int r0 = mi * 32 + mt * 16 + t4;
        #pragma unroll
        for (int nt = 0; nt < 8; nt++) {
            const int n0 = ni * 64 + nt * 8 + 2 * cl;
            float2 v0, v1;
            v0.x = f2tf(fmaxf(c1[mt][nt][0] + b1s[n0],     0.f));
            v0.y = f2tf(fmaxf(c1[mt][nt][1] + b1s[n0 + 1], 0.f));
            v1.x = f2tf(fmaxf(c1[mt][nt][2] + b1s[n0],     0.f));
            v1.y = f2tf(fmaxf(c1[mt][nt][3] + b1s[n0 + 1], 0.f));
            *(float2*)(sm + r0 * S_STR + n0)       = v0;
            *(float2*)(sm + (r0 + 8) * S_STR + n0) = v1;
        }
    }
    CP_WAIT0();
    __syncthreads();

    // ======================= layer 2: K=128, N=64 ===========================
    float c2[2][4][4];
    #pragma unroll
    for (int mt = 0; mt < 2; mt++)
        #pragma unroll
        for (int nt = 0; nt < 4; nt++)
            #pragma unroll
            for (int v = 0; v < 4; v++) c2[mt][nt][v] = 0.f;

    #pragma unroll 4
    for (int ks = 0; ks < 16; ks++) {
        uint32_t a[2][4];
        #pragma unroll
        for (int mt = 0; mt < 2; mt++) {
            const float* ap = sm + (mi * 32 + mt * 16 + t4) * S_STR + ks * 8 + cl;
            a[mt][0] = __float_as_uint(ap[0]);
            a[mt][1] = __float_as_uint(ap[8 * S_STR]);
            a[mt][2] = __float_as_uint(ap[4]);
            a[mt][3] = __float_as_uint(ap[8 * S_STR + 4]);
        }
        uint32_t b[4][2];
        #pragma unroll
        for (int np = 0; np < 2; np++) {
            int q = ni * 16 + np * 8 + t4;
            const char* bp = smem + SM_W2 + ((ks * 8 + cl) * W2_STR + q * 2) * 4;
            float2 p0 = *(const float2*)bp;
            float2 p1 = *(const float2*)(bp + 4 * W2_STR * 4);
            b[np][0]     = __float_as_uint(p0.x);
            b[np + 2][0] = __float_as_uint(p0.y);
            b[np][1]     = __float_as_uint(p1.x);
            b[np + 2][1] = __float_as_uint(p1.y);
        }
        #pragma unroll
        for (int mt = 0; mt < 2; mt++)
            #pragma unroll
            for (int nt = 0; nt < 4; nt++)
                MMA(c2[mt][nt], a[mt], b[nt]);
    }

    // ============ layer 3: score = relu(C2+b2) . W3  (+ b3 at the end) ======
    float* R = sm + (SM_R >> 2);
    #pragma unroll
    for (int mt = 0; mt < 2; mt++) {
        float p0 = 0.f, p1 = 0.f;
        #pragma unroll
        for (int nt = 0; nt < 4; nt++) {
            const int n0 = ni * 32 + nt * 8 + 2 * cl;
            const float w0 = w3s[n0], w1 = w3s[n0 + 1];
            const float g0 = b2s[n0], g1 = b2s[n0 + 1];
            p0 += fmaxf(c2[mt][nt][0] + g0, 0.f) * w0 + fmaxf(c2[mt][nt][1] + g1, 0.f) * w1;
            p1 += fmaxf(c2[mt][nt][2] + g0, 0.f) * w0 + fmaxf(c2[mt][nt][3] + g1, 0.f) * w1;
        }
        p0 += __shfl_xor_sync(0xffffffffu, p0, 1);
        p0 += __shfl_xor_sync(0xffffffffu, p0, 2);
        p1 += __shfl_xor_sync(0xffffffffu, p1, 1);
        p1 += __shfl_xor_sync(0xffffffffu, p1, 2);
        if (cl == 0) {
            const int r0 = mi * 32 + mt * 16 + t4;
            R[ni * 128 + r0]     = p0;
            R[ni * 128 + r0 + 8] = p1;
        }
    }
    __syncthreads();
    if (tid < 128) {
        const long long e = (long long)tile_base + tid;
        if (e < n_edges) out[e] = R[tid] + R[128 + tid] + b3s[0];
    }
}

// ---------------------------------------------------------------------------
extern "C" void kernel_launch(void* const* d_in, const int* in_sizes, int n_in,
                              void* d_out, int out_size) {
    const float* z  = (const float*)d_in[0];
    const void*  ei = (const void*) d_in[1];
    const float* W1 = (const float*)d_in[2];
    const float* b1 = (const float*)d_in[3];
    const float* W2 = (const float*)d_in[4];
    const float* b2 = (const float*)d_in[5];
    const float* W3 = (const float*)d_in[6];
    const float* b3 = (const float*)d_in[7];
    const int n = out_size;

    prep_weights<<<(512 * 64 + 128 * 32 + 255) / 256, 256>>>(W1, W2);

    cudaFuncSetAttribute(lp_main, cudaFuncAttributeMaxDynamicSharedMemorySize, SMEM_TOTAL);
    lp_main<<<(n + TE - 1) / TE, 256, SMEM_TOTAL>>>(z, ei, b1, b2, W3, b3, (float*)d_out, n);
}

// round 4
// speedup vs baseline: 1.9907x; 1.9907x over previous
#include <cuda_runtime.h>
#include <cstdint>

// ============================================================================
// LinkPredictor, mma.sync tf32 (sm_103 target: no tcgen05).
// Round-3: 2 CTAs/SM (110KB smem), j-panel streamed gather via cp.async,
// register-built product/|diff| fragments (no P/Q smem build).
//   layer1: A[128,512] @ W1[512,128] -> C1 (regs)
//   layer2: relu(C1+b1)[128,128] @ W2[128,64] -> C2 (regs)
//   layer3: relu(C2+b2) . W3 + b3 -> out[E]
// ============================================================================

#define TE 128

// prep scratch: tf32-converted, pair-interleaved weights
__device__ __align__(16) float2 g_W1p[512 * 64];   // [k][q], {n_q, n_q+32}, n_q=(q&31)+(q>>5)*64
__device__ __align__(16) float2 g_W2p[128 * 32];   // [k][q], {n_q, n_q+16}, n_q=(q&15)+(q>>4)*32

// ---- smem geometry (word strides: mod 32 = 4 or 8 -> conflict-free frags) ----
#define PAN_STR   36          // panel row words (32 data + 4 pad), mod32=4
#define PAN_HALF  4608        // words per (s or d) half: 128*36
#define PAN_BUF   9216        // words per j-buffer (s+d)
#define B1_STR    136         // B row words (64 float2 + pad), mod32=8
#define W2_STR    72          // mod32=8
#define A2_STR    132         // mod32=4

#define SM_PAN    0           // 2 j-buffers: 2*9216*4 = 73728 B
#define SM_B1     73728       // 2 chunk buffers x 32*544 = 34816 B  (end 108544)
#define B1_BUF    17408
#define SM_A2     0           // phase2: [128][132] f32 = 67584 B (over panels)
#define SM_W2     67584       // phase2: 128*288 = 36864 B (end 104448, over B1)
#define SM_R      104448      // [2][128] f32 = 1024 B
#define SM_SMALL  108544      // b1[128]|b2[64]|w3[64]|b3
#define SMEM_TOTAL 109600

__device__ __forceinline__ uint32_t smem_u32(const void* p) {
    uint32_t a;
    asm("{ .reg .u64 t; cvta.to.shared.u64 t, %1; cvt.u32.u64 %0, t; }" : "=r"(a) : "l"(p));
    return a;
}
__device__ __forceinline__ float f2tf(float f) {
    uint32_t r; asm("cvt.rna.tf32.f32 %0, %1;" : "=r"(r) : "f"(f));
    return __uint_as_float(r);
}
__device__ __forceinline__ uint32_t f2tfu(float f) {
    uint32_t r; asm("cvt.rna.tf32.f32 %0, %1;" : "=r"(r) : "f"(f));
    return r;
}
__device__ __forceinline__ void cp16(uint32_t d, const void* s) {
    asm volatile("cp.async.ca.shared.global [%0], [%1], 16;" :: "r"(d), "l"(s) : "memory");
}
#define CP_COMMIT() asm volatile("cp.async.commit_group;" ::: "memory")
#define CP_WAIT0()  asm volatile("cp.async.wait_group 0;"  ::: "memory")
#define CP_WAIT1()  asm volatile("cp.async.wait_group 1;"  ::: "memory")

#define MMA(c, a, b)                                                           \
    asm volatile("mma.sync.aligned.m16n8k8.row.col.f32.tf32.tf32.f32 "         \
                 "{%0,%1,%2,%3}, {%4,%5,%6,%7}, {%8,%9}, {%0,%1,%2,%3};"       \
                 : "+f"((c)[0]), "+f"((c)[1]), "+f"((c)[2]), "+f"((c)[3])      \
                 : "r"((a)[0]), "r"((a)[1]), "r"((a)[2]), "r"((a)[3]),         \
                   "r"((b)[0]), "r"((b)[1]))

// ---------------------------------------------------------------------------
__global__ void prep_weights(const float* __restrict__ W1, const float* __restrict__ W2) {
    int i = blockIdx.x * blockDim.x + threadIdx.x;
    if (i < 512 * 64) {
        int k = i >> 6, q = i & 63;
        int n = (q & 31) + ((q >> 5) << 6);
        float2 v;
        v.x = f2tf(W1[k * 128 + n]);
        v.y = f2tf(W1[k * 128 + n + 32]);
        g_W1p[i] = v;
    } else {
        int j = i - 512 * 64;
        if (j < 128 * 32) {
            int k = j >> 5, q = j & 31;
            int n = (q & 15) + ((q >> 4) << 5);
            float2 v;
            v.x = f2tf(W2[k * 64 + n]);
            v.y = f2tf(W2[k * 64 + n + 16]);
            g_W2p[j] = v;
        }
    }
}

// ---------------------------------------------------------------------------
// layer-1 chunk consumer: A frags from panel (s/d/prod/absdiff in regs)
// ---------------------------------------------------------------------------
template<int FB>
__device__ __forceinline__ void l1_chunk(const float* __restrict__ Sp,
                                         const float* __restrict__ Dp,
                                         const char*  __restrict__ Bb,
                                         float (&c1)[2][8][4],
                                         int mi, int ni, int t4, int cl)
{
    #pragma unroll
    for (int ks = 0; ks < 4; ks++) {
        uint32_t a[2][4];
        #pragma unroll
        for (int mt = 0; mt < 2; mt++) {
            const int ro = (mi * 32 + mt * 16 + t4) * PAN_STR + ks * 8 + cl;
            if (FB == 0) {
                a[mt][0] = f2tfu(Sp[ro]);               a[mt][1] = f2tfu(Sp[ro + 8*PAN_STR]);
                a[mt][2] = f2tfu(Sp[ro + 4]);           a[mt][3] = f2tfu(Sp[ro + 8*PAN_STR + 4]);
            } else if (FB == 1) {
                a[mt][0] = f2tfu(Dp[ro]);               a[mt][1] = f2tfu(Dp[ro + 8*PAN_STR]);
                a[mt][2] = f2tfu(Dp[ro + 4]);           a[mt][3] = f2tfu(Dp[ro + 8*PAN_STR + 4]);
            } else {
                float s0 = Sp[ro],     s1 = Sp[ro + 8*PAN_STR];
                float s2 = Sp[ro + 4], s3 = Sp[ro + 8*PAN_STR + 4];
                float d0 = Dp[ro],     d1 = Dp[ro + 8*PAN_STR];
                float d2 = Dp[ro + 4], d3 = Dp[ro + 8*PAN_STR + 4];
                if (FB == 2) {
                    a[mt][0] = f2tfu(s0*d0); a[mt][1] = f2tfu(s1*d1);
                    a[mt][2] = f2tfu(s2*d2); a[mt][3] = f2tfu(s3*d3);
                } else {
                    a[mt][0] = f2tfu(fabsf(s0-d0)); a[mt][1] = f2tfu(fabsf(s1-d1));
                    a[mt][2] = f2tfu(fabsf(s2-d2)); a[mt][3] = f2tfu(fabsf(s3-d3));
                }
            }
        }
        uint32_t b[8][2];
        #pragma unroll
        for (int np = 0; np < 4; np++) {
            int q = ni * 32 + np * 8 + t4;
            const char* bp = Bb + ((ks * 8 + cl) * B1_STR + q * 2) * 4;
            float2 p0 = *(const float2*)bp;
            float2 p1 = *(const float2*)(bp + 4 * B1_STR * 4);
            b[np][0]     = __float_as_uint(p0.x);
            b[np + 4][0] = __float_as_uint(p0.y);
            b[np][1]     = __float_as_uint(p1.x);
            b[np + 4][1] = __float_as_uint(p1.y);
        }
        #pragma unroll
        for (int mt = 0; mt < 2; mt++)
            #pragma unroll
            for (int nt = 0; nt < 8; nt++)
                MMA(c1[mt][nt], a[mt], b[nt]);
    }
}

// stage one B chunk (32 k-rows of pair-interleaved W1) into buffer buf
__device__ __forceinline__ void stage_B(uint32_t sbase, int buf, int kc, int tid) {
    #pragma unroll
    for (int r = 0; r < 4; r++) {
        int q = tid + 256 * r;
        int row = q >> 5, seg = q & 31;
        cp16(sbase + SM_B1 + buf * B1_BUF + row * (B1_STR * 4) + seg * 16,
             (const char*)(g_W1p + (kc + row) * 64) + seg * 16);
    }
}

// stage this thread's 128B slice of panel j (thread owns edge le, half h)
__device__ __forceinline__ void stage_panel(uint32_t sbase, const float* __restrict__ z,
                                            int jbuf, int j, int gidx, int le, int h) {
    uint32_t dst = sbase + SM_PAN + (uint32_t)jbuf * (PAN_BUF * 4)
                 + (uint32_t)h * (PAN_HALF * 4) + (uint32_t)le * (PAN_STR * 4);
    const float* src = z + (long long)gidx * 128 + j * 32;
    #pragma unroll
    for (int s = 0; s < 8; s++) cp16(dst + s * 16, src + s * 4);
}

// ---------------------------------------------------------------------------
__global__ void __launch_bounds__(256, 2)
lp_main(const float* __restrict__ z,
        const void*  __restrict__ eiv,
        const float* __restrict__ b1,
        const float* __restrict__ b2,
        const float* __restrict__ W3,
        const float* __restrict__ b3,
        float* __restrict__ out,
        int n_edges)
{
    extern __shared__ char smem[];
    float* sm = (float*)smem;
    const uint32_t sbase = smem_u32(smem);
    const int tid  = threadIdx.x;
    const int lane = tid & 31;
    const int wid  = tid >> 5;
    const int mi   = wid >> 1;       // 4 m-slabs of 32 rows
    const int ni   = wid & 1;        // 2 n-halves
    const int t4   = lane >> 2;
    const int cl   = lane & 3;
    const int tile_base = blockIdx.x * TE;

    float* b1s = sm + (SM_SMALL >> 2);
    float* b2s = b1s + 128;
    float* w3s = b2s + 64;
    float* b3s = w3s + 64;

    if (tid < 128) b1s[tid] = b1[tid];
    if (tid < 64) { b2s[tid] = b2[tid]; w3s[tid] = W3[tid]; }
    if (tid == 0)  b3s[0] = b3[0];

    // ---- per-thread edge index (thread owns edge le, src(h=0)/dst(h=1)) ----
    const int le = tid >> 1, h = tid & 1;
    const long long eg = (long long)tile_base + le;
    int gidx = 0;
    {
        const unsigned* p = (const unsigned*)eiv;
        unsigned orv = 0;
        #pragma unroll
        for (int i = 0; i < 16; i++) orv |= p[2 * i + 1];
        const bool is64 = (orv == 0);
        if (eg < n_edges) {
            if (is64) {
                const long long* e64 = (const long long*)eiv;
                gidx = (int)(h ? e64[(long long)n_edges + eg] : e64[eg]);
            } else {
                const int* e32 = (const int*)eiv;
                gidx = h ? e32[n_edges + eg] : e32[eg];
            }
        }
    }

    // ---- prologue prefetch: panel 0, B chunk 0 ----
    stage_panel(sbase, z, 0, 0, gidx, le, h); CP_COMMIT();
    stage_B(sbase, 0, 0, tid);               CP_COMMIT();

    float c1[2][8][4];
    #pragma unroll
    for (int mt = 0; mt < 2; mt++)
        #pragma unroll
        for (int nt = 0; nt < 8; nt++)
            #pragma unroll
            for (int v = 0; v < 4; v++) c1[mt][nt][v] = 0.f;

    // =============== layer 1: 16 chunks (j outer, fb inner) =================
    #pragma unroll 1
    for (int c = 0; c < 16; c++) {
        const int j = c >> 2, fb = c & 3;

        // wait: need B(c) and panel(j); a not-yet-needed P(j+1) may stay pending
        if (fb == 3 && j < 3) CP_WAIT1(); else CP_WAIT0();
        __syncthreads();                       // all warps done with prev buffers

        if (c < 15) {                          // prefetch next B chunk
            const int cn = c + 1, fbn = cn & 3, jn = cn >> 2;
            stage_B(sbase, cn & 1, fbn * 128 + jn * 32, tid);
            CP_COMMIT();
        }
        if (fb == 2 && j < 3) {                // prefetch next panel (2-chunk slack)
            stage_panel(sbase, z, (j + 1) & 1, j + 1, gidx, le, h);
            CP_COMMIT();
        }

        const float* Sp = sm + (j & 1) * PAN_BUF;
        const float* Dp = Sp + PAN_HALF;
        const char*  Bb = smem + SM_B1 + (c & 1) * B1_BUF;
        if      (fb == 0) l1_chunk<0>(Sp, Dp, Bb, c1, mi, ni, t4, cl);
        else if (fb == 1) l1_chunk<1>(Sp, Dp, Bb, c1, mi, ni, t4, cl);
        else if (fb == 2) l1_chunk<2>(Sp, Dp, Bb, c1, mi, ni, t4, cl);
        else              l1_chunk<3>(Sp, Dp, Bb, c1, mi, ni, t4, cl);
    }
    __syncthreads();   // all panel/B reads done; safe to overlay A2/W2

    // ---- stage W2 (overlaps epilogue-1 math) ----
    {
        #pragma unroll
        for (int r = 0; r < 8; r++) {
            int q = tid + 256 * r;
            int row = q >> 4, seg = q & 15;
            cp16(sbase + SM_W2 + row * (W2_STR * 4) + seg * 16,
                 (const char*)(g_W2p + row * 32) + seg * 16);
        }
        CP_COMMIT();
    }

    // ---- epilogue 1: A2 = tf32(relu(C1 + b1)) ----
    #pragma unroll
    for (int mt = 0; mt < 2; mt++) {
        const int r0 = mi * 32 + mt * 16 + t4;
        #pragma unroll
        for (int nt = 0; nt < 8; nt++) {
            const int n0 = ni * 64 + nt * 8 + 2 * cl;
            float2 v0, v1;
            v0.x = f2tf(fmaxf(c1[mt][nt][0] + b1s[n0],     0.f));
            v0.y = f2tf(fmaxf(c1[mt][nt][1] + b1s[n0 + 1], 0.f));
            v1.x = f2tf(fmaxf(c1[mt][nt][2] + b1s[n0],     0.f));
            v1.y = f2tf(fmaxf(c1[mt][nt][3] + b1s[n0 + 1], 0.f));
            *(float2*)(sm + r0 * A2_STR + n0)       = v0;
            *(float2*)(sm + (r0 + 8) * A2_STR + n0) = v1;
        }
    }
    CP_WAIT0();
    __syncthreads();

    // =============== layer 2: K=128, N=64 ===================================
    float c2[2][4][4];
    #pragma unroll
    for (int mt = 0; mt < 2; mt++)
        #pragma unroll
        for (int nt = 0; nt < 4; nt++)
            #pragma unroll
            for (int v = 0; v < 4; v++) c2[mt][nt][v] = 0.f;

    #pragma unroll 4
    for (int ks = 0; ks < 16; ks++) {
        uint32_t a[2][4];
        #pragma unroll
        for (int mt = 0; mt < 2; mt++) {
            const float* ap = sm + (mi * 32 + mt * 16 + t4) * A2_STR + ks * 8 + cl;
            a[mt][0] = __float_as_uint(ap[0]);
            a[mt][1] = __float_as_uint(ap[8 * A2_STR]);
            a[mt][2] = __float_as_uint(ap[4]);
            a[mt][3] = __float_as_uint(ap[8 * A2_STR + 4]);
        }
        uint32_t b[4][2];
        #pragma unroll
        for (int np = 0; np < 2; np++) {
            int q = ni * 16 + np * 8 + t4;
            const char* bp = smem + SM_W2 + ((ks * 8 + cl) * W2_STR + q * 2) * 4;
            float2 p0 = *(const float2*)bp;
            float2 p1 = *(const float2*)(bp + 4 * W2_STR * 4);
            b[np][0]     = __float_as_uint(p0.x);
            b[np + 2][0] = __float_as_uint(p0.y);
            b[np][1]     = __float_as_uint(p1.x);
            b[np + 2][1] = __float_as_uint(p1.y);
        }
        #pragma unroll
        for (int mt = 0; mt < 2; mt++)
            #pragma unroll
            for (int nt = 0; nt < 4; nt++)
                MMA(c2[mt][nt], a[mt], b[nt]);
    }

    // =============== layer 3: relu(C2+b2) . W3 + b3 =========================
    float* R = sm + (SM_R >> 2);
    #pragma unroll
    for (int mt = 0; mt < 2; mt++) {
        float p0 = 0.f, p1 = 0.f;
        #pragma unroll
        for (int nt = 0; nt < 4; nt++) {
            const int n0 = ni * 32 + nt * 8 + 2 * cl;
            const float w0 = w3s[n0], w1 = w3s[n0 + 1];
            const float g0 = b2s[n0], g1 = b2s[n0 + 1];
            p0 += fmaxf(c2[mt][nt][0] + g0, 0.f) * w0 + fmaxf(c2[mt][nt][1] + g1, 0.f) * w1;
            p1 += fmaxf(c2[mt][nt][2] + g0, 0.f) * w0 + fmaxf(c2[mt][nt][3] + g1, 0.f) * w1;
        }
        p0 += __shfl_xor_sync(0xffffffffu, p0, 1);
        p0 += __shfl_xor_sync(0xffffffffu, p0, 2);
        p1 += __shfl_xor_sync(0xffffffffu, p1, 1);
        p1 += __shfl_xor_sync(0xffffffffu, p1, 2);
        if (cl == 0) {
            const int r0 = mi * 32 + mt * 16 + t4;
            R[ni * 128 + r0]     = p0;
            R[ni * 128 + r0 + 8] = p1;
        }
    }
    __syncthreads();
    if (tid < 128) {
        const long long e = (long long)tile_base + tid;
        if (e < n_edges) out[e] = R[tid] + R[128 + tid] + b3s[0];
    }
}

// ---------------------------------------------------------------------------
extern "C" void kernel_launch(void* const* d_in, const int* in_sizes, int n_in,
                              void* d_out, int out_size) {
    const float* z  = (const float*)d_in[0];
    const void*  ei = (const void*) d_in[1];
    const float* W1 = (const float*)d_in[2];
    const float* b1 = (const float*)d_in[3];
    const float* W2 = (const float*)d_in[4];
    const float* b2 = (const float*)d_in[5];
    const float* W3 = (const float*)d_in[6];
    const float* b3 = (const float*)d_in[7];
    const int n = out_size;

    prep_weights<<<(512 * 64 + 128 * 32 + 255) / 256, 256>>>(W1, W2);

    cudaFuncSetAttribute(lp_main, cudaFuncAttributeMaxDynamicSharedMemorySize, SMEM_TOTAL);
    lp_main<<<(n + TE - 1) / TE, 256, SMEM_TOTAL>>>(z, ei, b1, b2, W3, b3, (float*)d_out, n);
}

// round 6
// speedup vs baseline: 2.5968x; 1.3045x over previous
#include <cuda_runtime.h>
#include <cuda_fp16.h>
#include <cstdint>

// ============================================================================
// LinkPredictor, sm_103 (no tcgen05): layer-1 via mma.sync fp16 m16n8k16
// (fp32 accum), layer-2 tf32 m16n8k8, layer-3 SIMT.
// Per 128-edge CTA tile, per j-panel (32 cols of H):
//   gather fp32 s/d staging -> build 4 fp16 feature panels once ->
//   4 chunk GEMMs vs double-buffered fp16 W1 chunks.
// R6 fix: chunk c=4j+fb must stage W1 k-rows fb*128 + j*32 (feature-block-
// major); round-5 erroneously staged 16*c (j-major) -> wrong W1 rows.
// ============================================================================

#define TE 128

// prep scratch
__device__ __align__(16) uint2  g_W1h[256 * 64];   // [kp][q]: half2{W1[2kp][n],W1[2kp+1][n]} for n=nq, nq+32
__device__ __align__(16) float2 g_W2p[128 * 32];   // tf32 pair-interleaved (layer 2)

// ---- smem geometry ----
#define STG_STR   36                  // fp32 staging row words (32+4 pad)
#define SM_STG    0                   // s[128][36w] + d[128][36w] = 36864 B
#define SM_FEAT   36864               // 4 fp16 panels x 128 rows x 20 granules(4B) = 40960 B
#define FEAT_PAN  10240
#define FEAT_RSTR 20                  // granules (uint32) per row
#define SM_B1     77824               // 2 x 16 kp-rows x 544B = 17408 B  (end 95232)
#define B1_BUF    8704
#define B1_STR    136                 // words per kp row (128 data + 8 pad)
// phase 2 (overlays phase 1):
#define A2_STR    132
#define SM_A2     0                   // [128][132w] f32 = 67584
#define SM_W2     67584               // 128 x 72w = 36864 (end 104448)
#define W2_STR    72
#define SM_R      104448              // [2][128] f32 = 1024
#define SM_SMALL  105472              // b1[128]|b2[64]|w3[64]|b3
#define SMEM_TOTAL 106528

__device__ __forceinline__ uint32_t smem_u32(const void* p) {
    uint32_t a;
    asm("{ .reg .u64 t; cvta.to.shared.u64 t, %1; cvt.u32.u64 %0, t; }" : "=r"(a) : "l"(p));
    return a;
}
__device__ __forceinline__ float f2tf(float f) {
    uint32_t r; asm("cvt.rna.tf32.f32 %0, %1;" : "=r"(r) : "f"(f));
    return __uint_as_float(r);
}
__device__ __forceinline__ void cp16(uint32_t d, const void* s) {
    asm volatile("cp.async.ca.shared.global [%0], [%1], 16;" :: "r"(d), "l"(s) : "memory");
}
#define CP_COMMIT() asm volatile("cp.async.commit_group;" ::: "memory")
#define CP_WAIT0()  asm volatile("cp.async.wait_group 0;"  ::: "memory")
#define CP_WAIT1()  asm volatile("cp.async.wait_group 1;"  ::: "memory")

// fp16 m16n8k16, fp32 accum
#define MMA16(c, a, b)                                                          \
    asm volatile("mma.sync.aligned.m16n8k16.row.col.f32.f16.f16.f32 "           \
                 "{%0,%1,%2,%3}, {%4,%5,%6,%7}, {%8,%9}, {%0,%1,%2,%3};"        \
                 : "+f"((c)[0]), "+f"((c)[1]), "+f"((c)[2]), "+f"((c)[3])       \
                 : "r"((a)[0]), "r"((a)[1]), "r"((a)[2]), "r"((a)[3]),          \
                   "r"((b)[0]), "r"((b)[1]))
// tf32 m16n8k8 (layer 2)
#define MMA8(c, a, b)                                                           \
    asm volatile("mma.sync.aligned.m16n8k8.row.col.f32.tf32.tf32.f32 "          \
                 "{%0,%1,%2,%3}, {%4,%5,%6,%7}, {%8,%9}, {%0,%1,%2,%3};"        \
                 : "+f"((c)[0]), "+f"((c)[1]), "+f"((c)[2]), "+f"((c)[3])       \
                 : "r"((a)[0]), "r"((a)[1]), "r"((a)[2]), "r"((a)[3]),          \
                   "r"((b)[0]), "r"((b)[1]))

// ---------------------------------------------------------------------------
__global__ void prep_weights(const float* __restrict__ W1, const float* __restrict__ W2) {
    int i = blockIdx.x * blockDim.x + threadIdx.x;
    if (i < 256 * 64) {
        int kp = i >> 6, q = i & 63;
        int n = (q & 31) + ((q >> 5) << 6);
        uint2 v;
        __half2 lo = __floats2half2_rn(W1[(2*kp) * 128 + n],      W1[(2*kp+1) * 128 + n]);
        __half2 hi = __floats2half2_rn(W1[(2*kp) * 128 + n + 32], W1[(2*kp+1) * 128 + n + 32]);
        v.x = *(uint32_t*)&lo;  v.y = *(uint32_t*)&hi;
        g_W1h[i] = v;
    } else {
        int j = i - 256 * 64;
        if (j < 128 * 32) {
            int k = j >> 5, q = j & 31;
            int n = (q & 15) + ((q >> 4) << 5);
            float2 v;
            v.x = f2tf(W2[k * 64 + n]);
            v.y = f2tf(W2[k * 64 + n + 16]);
            g_W2p[j] = v;
        }
    }
}

// ---------------------------------------------------------------------------
// layer-1 chunk: fp16 feature panel x fp16 B chunk (K=32 -> 2 k-steps)
// ---------------------------------------------------------------------------
__device__ __forceinline__ void l1_chunk(const uint32_t* __restrict__ F,
                                         const char*     __restrict__ Bb,
                                         float (&c1)[2][8][4],
                                         int mi, int ni, int t4, int cl)
{
    #pragma unroll
    for (int ks = 0; ks < 2; ks++) {
        uint32_t a[2][4];
        #pragma unroll
        for (int mt = 0; mt < 2; mt++) {
            const int g0 = (mi * 32 + mt * 16 + t4) * FEAT_RSTR + cl + 8 * ks;
            a[mt][0] = F[g0];
            a[mt][1] = F[g0 + 8 * FEAT_RSTR];
            a[mt][2] = F[g0 + 4];
            a[mt][3] = F[g0 + 4 + 8 * FEAT_RSTR];
        }
        uint32_t b[8][2];
        #pragma unroll
        for (int np = 0; np < 4; np++) {
            const int q = ni * 32 + np * 8 + t4;
            const char* bp = Bb + ((8 * ks + cl) * B1_STR + q * 2) * 4;
            uint2 p0 = *(const uint2*)bp;                        // kp rows cl (+8ks)
            uint2 p1 = *(const uint2*)(bp + 4 * B1_STR * 4);     // kp rows cl+4 (+8ks)
            b[np][0]     = p0.x;  b[np + 4][0] = p0.y;
            b[np][1]     = p1.x;  b[np + 4][1] = p1.y;
        }
        #pragma unroll
        for (int mt = 0; mt < 2; mt++)
            #pragma unroll
            for (int nt = 0; nt < 8; nt++)
                MMA16(c1[mt][nt], a[mt], b[nt]);
    }
}

// stage one fp16 B chunk for c=4j+fb: W1 k-rows fb*128 + j*32 (kp = fb*64+j*16)
__device__ __forceinline__ void stage_B(uint32_t sbase, int buf, int chunk, int tid) {
    const int kc = ((chunk & 3) << 6) + ((chunk >> 2) << 4);   // kp base, feature-block-major
    #pragma unroll
    for (int r = 0; r < 2; r++) {
        int q = tid + 256 * r;
        int row = q >> 5, seg = q & 31;
        cp16(sbase + SM_B1 + buf * B1_BUF + row * (B1_STR * 4) + seg * 16,
             (const char*)(g_W1h + (kc + row) * 64) + seg * 16);
    }
}

// stage this thread's 128B slice of fp32 staging for panel j
__device__ __forceinline__ void stage_panel(uint32_t sbase, const float* __restrict__ z,
                                            int j, int gidx, int le, int h) {
    uint32_t dst = sbase + SM_STG + (uint32_t)h * (128 * STG_STR * 4)
                 + (uint32_t)le * (STG_STR * 4);
    const float* src = z + (long long)gidx * 128 + j * 32;
    #pragma unroll
    for (int s = 0; s < 8; s++) cp16(dst + s * 16, src + s * 4);
}

// ---------------------------------------------------------------------------
__global__ void __launch_bounds__(256, 2)
lp_main(const float* __restrict__ z,
        const void*  __restrict__ eiv,
        const float* __restrict__ b1,
        const float* __restrict__ b2,
        const float* __restrict__ W3,
        const float* __restrict__ b3,
        float* __restrict__ out,
        int n_edges)
{
    extern __shared__ char smem[];
    float* sm = (float*)smem;
    const uint32_t sbase = smem_u32(smem);
    const int tid  = threadIdx.x;
    const int lane = tid & 31;
    const int wid  = tid >> 5;
    const int mi   = wid >> 1;
    const int ni   = wid & 1;
    const int t4   = lane >> 2;
    const int cl   = lane & 3;
    const int tile_base = blockIdx.x * TE;

    float* b1s = sm + (SM_SMALL >> 2);
    float* b2s = b1s + 128;
    float* w3s = b2s + 64;
    float* b3s = w3s + 64;

    if (tid < 128) b1s[tid] = b1[tid];
    if (tid < 64) { b2s[tid] = b2[tid]; w3s[tid] = W3[tid]; }
    if (tid == 0)  b3s[0] = b3[0];

    // ---- per-thread edge index (thread owns edge le; h: 0=src 1=dst) ----
    const int le = tid >> 1, h = tid & 1;
    const long long eg = (long long)tile_base + le;
    int gidx = 0;
    {
        const unsigned* p = (const unsigned*)eiv;
        unsigned orv = 0;
        #pragma unroll
        for (int i = 0; i < 16; i++) orv |= p[2 * i + 1];
        if (eg < n_edges) {
            if (orv == 0) {   // int64 indices
                const long long* e64 = (const long long*)eiv;
                gidx = (int)(h ? e64[(long long)n_edges + eg] : e64[eg]);
            } else {
                const int* e32 = (const int*)eiv;
                gidx = h ? e32[n_edges + eg] : e32[eg];
            }
        }
    }

    // ---- prologue: staging(0), B(0) ----
    stage_panel(sbase, z, 0, gidx, le, h); CP_COMMIT();
    stage_B(sbase, 0, 0, tid);             CP_COMMIT();

    float c1[2][8][4];
    #pragma unroll
    for (int mt = 0; mt < 2; mt++)
        #pragma unroll
        for (int nt = 0; nt < 8; nt++)
            #pragma unroll
            for (int v = 0; v < 4; v++) c1[mt][nt][v] = 0.f;

    const uint32_t* Fs = (const uint32_t*)(smem + SM_FEAT);
    const int brow = tid >> 1, bh = tid & 1;      // build: row, column-half

    // =============== layer 1: 4 j-panels x 4 feature chunks =================
    #pragma unroll 1
    for (int j = 0; j < 4; j++) {
        CP_WAIT0();           // staging(j) + B(4j) landed
        __syncthreads();

        // ---- build 4 fp16 feature panels from fp32 staging ----
        {
            const float4* Sr = (const float4*)(smem + SM_STG + brow * (STG_STR * 4) + bh * 64);
            const float4* Dr = (const float4*)(smem + SM_STG + 128 * STG_STR * 4 + brow * (STG_STR * 4) + bh * 64);
            uint32_t us[8], ud[8], up[8], uq[8];
            #pragma unroll
            for (int i = 0; i < 4; i++) {
                float4 s4 = Sr[i], d4 = Dr[i];
                __half2 t;
                t = __floats2half2_rn(s4.x, s4.y);                       us[2*i]   = *(uint32_t*)&t;
                t = __floats2half2_rn(s4.z, s4.w);                       us[2*i+1] = *(uint32_t*)&t;
                t = __floats2half2_rn(d4.x, d4.y);                       ud[2*i]   = *(uint32_t*)&t;
                t = __floats2half2_rn(d4.z, d4.w);                       ud[2*i+1] = *(uint32_t*)&t;
                t = __floats2half2_rn(s4.x*d4.x, s4.y*d4.y);             up[2*i]   = *(uint32_t*)&t;
                t = __floats2half2_rn(s4.z*d4.z, s4.w*d4.w);             up[2*i+1] = *(uint32_t*)&t;
                t = __floats2half2_rn(fabsf(s4.x-d4.x), fabsf(s4.y-d4.y)); uq[2*i]   = *(uint32_t*)&t;
                t = __floats2half2_rn(fabsf(s4.z-d4.z), fabsf(s4.w-d4.w)); uq[2*i+1] = *(uint32_t*)&t;
            }
            uint32_t* F0 = (uint32_t*)(smem + SM_FEAT) + brow * FEAT_RSTR + bh * 8;
            #pragma unroll
            for (int pnl = 0; pnl < 4; pnl++) {
                const uint32_t* src = (pnl == 0) ? us : (pnl == 1) ? ud : (pnl == 2) ? up : uq;
                uint32_t* Fp = F0 + pnl * (FEAT_PAN >> 2);
                *(uint4*)(Fp)     = make_uint4(src[0], src[1], src[2], src[3]);
                *(uint4*)(Fp + 4) = make_uint4(src[4], src[5], src[6], src[7]);
            }
        }
        __syncthreads();      // features(j) ready

        #pragma unroll 1
        for (int fb = 0; fb < 4; fb++) {
            const int c = 4 * j + fb;
            if (fb == 1)      { CP_WAIT0(); __syncthreads(); }   // drains B(c)
            else if (fb == 2) { CP_WAIT1(); __syncthreads(); }   // drains B(c), keeps staging
            else if (fb == 3) { CP_WAIT0(); __syncthreads(); }   // drains staging + B(c)

            if (c < 15) { stage_B(sbase, (c + 1) & 1, c + 1, tid); CP_COMMIT(); }
            if (fb == 1) {                     // staging(j+1) (dummy group if j==3)
                if (j < 3) stage_panel(sbase, z, j + 1, gidx, le, h);
                CP_COMMIT();
            }

            l1_chunk(Fs + fb * (FEAT_PAN >> 2), smem + SM_B1 + (c & 1) * B1_BUF,
                     c1, mi, ni, t4, cl);
        }
    }
    __syncthreads();   // all phase-1 reads done; safe to overlay A2/W2

    // ---- stage W2 (tf32, overlaps epilogue-1) ----
    {
        #pragma unroll
        for (int r = 0; r < 8; r++) {
            int q = tid + 256 * r;
            int row = q >> 4, seg = q & 15;
            cp16(sbase + SM_W2 + row * (W2_STR * 4) + seg * 16,
                 (const char*)(g_W2p + row * 32) + seg * 16);
        }
        CP_COMMIT();
    }

    // ---- epilogue 1: A2 = tf32(relu(C1 + b1)) ----
    #pragma unroll
    for (int mt = 0; mt < 2; mt++) {
        const int r0 = mi * 32 + mt * 16 + t4;
        #pragma unroll
        for (int nt = 0; nt < 8; nt++) {
            const int n0 = ni * 64 + nt * 8 + 2 * cl;
            float2 v0, v1;
            v0.x = f2tf(fmaxf(c1[mt][nt][0] + b1s[n0],     0.f));
            v0.y = f2tf(fmaxf(c1[mt][nt][1] + b1s[n0 + 1], 0.f));
            v1.x = f2tf(fmaxf(c1[mt][nt][2] + b1s[n0],     0.f));
            v1.y = f2tf(fmaxf(c1[mt][nt][3] + b1s[n0 + 1], 0.f));
            *(float2*)(sm + r0 * A2_STR + n0)       = v0;
            *(float2*)(sm + (r0 + 8) * A2_STR + n0) = v1;
        }
    }
    CP_WAIT0();
    __syncthreads();

    // =============== layer 2: tf32, K=128, N=64 =============================
    float c2[2][4][4];
    #pragma unroll
    for (int mt = 0; mt < 2; mt++)
        #pragma unroll
        for (int nt = 0; nt < 4; nt++)
            #pragma unroll
            for (int v = 0; v < 4; v++) c2[mt][nt][v] = 0.f;

    #pragma unroll 4
    for (int ks = 0; ks < 16; ks++) {
        uint32_t a[2][4];
        #pragma unroll
        for (int mt = 0; mt < 2; mt++) {
            const float* ap = sm + (mi * 32 + mt * 16 + t4) * A2_STR + ks * 8 + cl;
            a[mt][0] = __float_as_uint(ap[0]);
            a[mt][1] = __float_as_uint(ap[8 * A2_STR]);
            a[mt][2] = __float_as_uint(ap[4]);
            a[mt][3] = __float_as_uint(ap[8 * A2_STR + 4]);
        }
        uint32_t b[4][2];
        #pragma unroll
        for (int np = 0; np < 2; np++) {
            int q = ni * 16 + np * 8 + t4;
            const char* bp = smem + SM_W2 + ((ks * 8 + cl) * W2_STR + q * 2) * 4;
            float2 p0 = *(const float2*)bp;
            float2 p1 = *(const float2*)(bp + 4 * W2_STR * 4);
            b[np][0]     = __float_as_uint(p0.x);
            b[np + 2][0] = __float_as_uint(p0.y);
            b[np][1]     = __float_as_uint(p1.x);
            b[np + 2][1] = __float_as_uint(p1.y);
        }
        #pragma unroll
        for (int mt = 0; mt < 2; mt++)
            #pragma unroll
            for (int nt = 0; nt < 4; nt++)
                MMA8(c2[mt][nt], a[mt], b[nt]);
    }

    // =============== layer 3: relu(C2+b2) . W3 + b3 =========================
    float* R = sm + (SM_R >> 2);
    #pragma unroll
    for (int mt = 0; mt < 2; mt++) {
        float p0 = 0.f, p1 = 0.f;
        #pragma unroll
        for (int nt = 0; nt < 4; nt++) {
            const int n0 = ni * 32 + nt * 8 + 2 * cl;
            const float w0 = w3s[n0], w1 = w3s[n0 + 1];
            const float g0 = b2s[n0], g1 = b2s[n0 + 1];
            p0 += fmaxf(c2[mt][nt][0] + g0, 0.f) * w0 + fmaxf(c2[mt][nt][1] + g1, 0.f) * w1;
            p1 += fmaxf(c2[mt][nt][2] + g0, 0.f) * w0 + fmaxf(c2[mt][nt][3] + g1, 0.f) * w1;
        }
        p0 += __shfl_xor_sync(0xffffffffu, p0, 1);
        p0 += __shfl_xor_sync(0xffffffffu, p0, 2);
        p1 += __shfl_xor_sync(0xffffffffu, p1, 1);
        p1 += __shfl_xor_sync(0xffffffffu, p1, 2);
        if (cl == 0) {
            const int r0 = mi * 32 + mt * 16 + t4;
            R[ni * 128 + r0]     = p0;
            R[ni * 128 + r0 + 8] = p1;
        }
    }
    __syncthreads();
    if (tid < 128) {
        const long long e = (long long)tile_base + tid;
        if (e < n_edges) out[e] = R[tid] + R[128 + tid] + b3s[0];
    }
}

// ---------------------------------------------------------------------------
extern "C" void kernel_launch(void* const* d_in, const int* in_sizes, int n_in,
                              void* d_out, int out_size) {
    const float* z  = (const float*)d_in[0];
    const void*  ei = (const void*) d_in[1];
    const float* W1 = (const float*)d_in[2];
    const float* b1 = (const float*)d_in[3];
    const float* W2 = (const float*)d_in[4];
    const float* b2 = (const float*)d_in[5];
    const float* W3 = (const float*)d_in[6];
    const float* b3 = (const float*)d_in[7];
    const int n = out_size;

    prep_weights<<<(256 * 64 + 128 * 32 + 255) / 256, 256>>>(W1, W2);

    cudaFuncSetAttribute(lp_main, cudaFuncAttributeMaxDynamicSharedMemorySize, SMEM_TOTAL);
    lp_main<<<(n + TE - 1) / TE, 256, SMEM_TOTAL>>>(z, ei, b1, b2, W3, b3, (float*)d_out, n);
}

// round 8
// speedup vs baseline: 2.9585x; 1.1393x over previous
#include <cuda_runtime.h>
#include <cuda_fp16.h>
#include <cstdint>

// ============================================================================
// LinkPredictor, sm_103 (no tcgen05). All-fp16 mma.sync m16n8k16 (fp32 accum):
//   layer1: A[128,512] feat @ W1 -> c1 ; layer2: relu(c1+b1) @ W2 -> c2 ;
//   layer3: relu(c2+b2).W3+b3 -> out.
// R8 fix: A2 fp16 row stride 20 -> 68 (128 cols = 64 words; 20 was FEAT's
// 32-col stride -> rows overlapped, corrupting layer 2). Phase-2 overlays
// re-laid: A2H over STG, W2H over FEAT (staged after post-chunks sync).
// ============================================================================

#define TE 128

// prep scratch (fp16 pair-interleaved weights)
__device__ __align__(16) uint2 g_W1h[256 * 64];  // [kp][q]: half2{W1[2kp][n],W1[2kp+1][n]}, n=(q&31)+(q>>5)*64
__device__ __align__(16) uint2 g_W2h[64 * 32];   // [kp][q]: half2{W2[2kp][n],W2[2kp+1][n]}, n=(q&15)+(q>>4)*32

// ---- smem geometry ----
#define STG_STR   36                  // fp32 staging row words (32+4 pad); 36 mod 32 = 4
#define SM_STG    0                   // s[128][36w] + d[128][36w] = 36864 B
#define SM_FEAT   36864               // 4 fp16 panels x 128 x 20 words = 40960 B
#define FEAT_PAN  10240
#define FEAT_RSTR 20
#define SM_B1     77824               // 4 chunk buffers x 16 kp-rows x 544B = 34816 B (end 112640)
#define B1_CH     8704
#define B1_STR    136                 // words per kp row; 136 mod 32 = 8
#define SM_SMALL  112640              // b1[128]|b2[64]|w3[64]|b3
#define SMEM_TOTAL 113696
// phase 2 overlays (lifetimes: STG dead after build(j=3); FEAT/B dead after
// post-chunks sync):
#define SM_A2H    0                   // fp16 [128][68w] = 34816 B (STG region)
#define A2_RSTR   68                  // 64 data words + 4 pad; 68 mod 32 = 4
#define SM_W2H    36864               // 64 kp x 72w = 18432 B (FEAT region, end 55296)
#define W2_STR    72                  // 72 mod 32 = 8
#define SM_R      55296               // [2][128] f32 = 1024 B

__device__ __forceinline__ uint32_t smem_u32(const void* p) {
    uint32_t a;
    asm("{ .reg .u64 t; cvta.to.shared.u64 t, %1; cvt.u32.u64 %0, t; }" : "=r"(a) : "l"(p));
    return a;
}
__device__ __forceinline__ void cp16(uint32_t d, const void* s) {
    asm volatile("cp.async.ca.shared.global [%0], [%1], 16;" :: "r"(d), "l"(s) : "memory");
}
#define CP_COMMIT() asm volatile("cp.async.commit_group;" ::: "memory")
#define CP_WAIT0()  asm volatile("cp.async.wait_group 0;"  ::: "memory")

// fp16 m16n8k16, fp32 accum
#define MMA16(c, a, b)                                                          \
    asm volatile("mma.sync.aligned.m16n8k16.row.col.f32.f16.f16.f32 "           \
                 "{%0,%1,%2,%3}, {%4,%5,%6,%7}, {%8,%9}, {%0,%1,%2,%3};"        \
                 : "+f"((c)[0]), "+f"((c)[1]), "+f"((c)[2]), "+f"((c)[3])       \
                 : "r"((a)[0]), "r"((a)[1]), "r"((a)[2]), "r"((a)[3]),          \
                   "r"((b)[0]), "r"((b)[1]))

// ---------------------------------------------------------------------------
__global__ void prep_weights(const float* __restrict__ W1, const float* __restrict__ W2) {
    int i = blockIdx.x * blockDim.x + threadIdx.x;
    if (i < 256 * 64) {
        int kp = i >> 6, q = i & 63;
        int n = (q & 31) + ((q >> 5) << 6);
        uint2 v;
        __half2 lo = __floats2half2_rn(W1[(2*kp) * 128 + n],      W1[(2*kp+1) * 128 + n]);
        __half2 hi = __floats2half2_rn(W1[(2*kp) * 128 + n + 32], W1[(2*kp+1) * 128 + n + 32]);
        v.x = *(uint32_t*)&lo;  v.y = *(uint32_t*)&hi;
        g_W1h[i] = v;
    } else {
        int j = i - 256 * 64;
        if (j < 64 * 32) {
            int kp = j >> 5, q = j & 31;
            int n = (q & 15) + ((q >> 4) << 5);
            uint2 v;
            __half2 lo = __floats2half2_rn(W2[(2*kp) * 64 + n],      W2[(2*kp+1) * 64 + n]);
            __half2 hi = __floats2half2_rn(W2[(2*kp) * 64 + n + 16], W2[(2*kp+1) * 64 + n + 16]);
            v.x = *(uint32_t*)&lo;  v.y = *(uint32_t*)&hi;
            g_W2h[j] = v;
        }
    }
}

// ---------------------------------------------------------------------------
// layer-1 chunk: fp16 feature panel x fp16 B chunk (K=32 -> 2 k-steps)
// ---------------------------------------------------------------------------
__device__ __forceinline__ void l1_chunk(const uint32_t* __restrict__ F,
                                         const char*     __restrict__ Bb,
                                         float (&c1)[2][8][4],
                                         int mi, int ni, int t4, int cl)
{
    #pragma unroll
    for (int ks = 0; ks < 2; ks++) {
        uint32_t a[2][4];
        #pragma unroll
        for (int mt = 0; mt < 2; mt++) {
            const int g0 = (mi * 32 + mt * 16 + t4) * FEAT_RSTR + cl + 8 * ks;
            a[mt][0] = F[g0];
            a[mt][1] = F[g0 + 8 * FEAT_RSTR];
            a[mt][2] = F[g0 + 4];
            a[mt][3] = F[g0 + 4 + 8 * FEAT_RSTR];
        }
        uint32_t b[8][2];
        #pragma unroll
        for (int np = 0; np < 4; np++) {
            const int q = ni * 32 + np * 8 + t4;
            const char* bp = Bb + ((8 * ks + cl) * B1_STR + q * 2) * 4;
            uint2 p0 = *(const uint2*)bp;
            uint2 p1 = *(const uint2*)(bp + 4 * B1_STR * 4);
            b[np][0]     = p0.x;  b[np + 4][0] = p0.y;
            b[np][1]     = p1.x;  b[np + 4][1] = p1.y;
        }
        #pragma unroll
        for (int mt = 0; mt < 2; mt++)
            #pragma unroll
            for (int nt = 0; nt < 8; nt++)
                MMA16(c1[mt][nt], a[mt], b[nt]);
    }
}

// stage ALL 4 fp16 B chunks of panel j (chunk c=4j+fb -> kp base fb*64+j*16)
__device__ __forceinline__ void stage_B4(uint32_t sbase, int j, int tid) {
    #pragma unroll
    for (int fb = 0; fb < 4; fb++) {
        const int kc = (fb << 6) + (j << 4);
        #pragma unroll
        for (int r = 0; r < 2; r++) {
            int q = tid + 256 * r;
            int row = q >> 5, seg = q & 31;
            cp16(sbase + SM_B1 + fb * B1_CH + row * (B1_STR * 4) + seg * 16,
                 (const char*)(g_W1h + (kc + row) * 64) + seg * 16);
        }
    }
}

// stage this thread's 128B slice of fp32 staging for panel j
__device__ __forceinline__ void stage_panel(uint32_t sbase, const float* __restrict__ z,
                                            int j, int gidx, int le, int h) {
    uint32_t dst = sbase + SM_STG + (uint32_t)h * (128 * STG_STR * 4)
                 + (uint32_t)le * (STG_STR * 4);
    const float* src = z + (long long)gidx * 128 + j * 32;
    #pragma unroll
    for (int s = 0; s < 8; s++) cp16(dst + s * 16, src + s * 4);
}

// stage W2h (64 kp rows x 256B) into FEAT region
__device__ __forceinline__ void stage_W2h(uint32_t sbase, int tid) {
    #pragma unroll
    for (int r = 0; r < 4; r++) {
        int i = tid + 256 * r;
        int row = i >> 4, seg = i & 15;
        cp16(sbase + SM_W2H + row * (W2_STR * 4) + seg * 16,
             (const char*)(g_W2h + row * 32) + seg * 16);
    }
}

// ---------------------------------------------------------------------------
__global__ void __launch_bounds__(256, 2)
lp_main(const float* __restrict__ z,
        const void*  __restrict__ eiv,
        const float* __restrict__ b1,
        const float* __restrict__ b2,
        const float* __restrict__ W3,
        const float* __restrict__ b3,
        float* __restrict__ out,
        int n_edges)
{
    extern __shared__ char smem[];
    float* sm = (float*)smem;
    const uint32_t sbase = smem_u32(smem);
    const int tid  = threadIdx.x;
    const int lane = tid & 31;
    const int wid  = tid >> 5;
    const int mi   = wid >> 1;
    const int ni   = wid & 1;
    const int t4   = lane >> 2;
    const int cl   = lane & 3;
    const int tile_base = blockIdx.x * TE;

    float* b1s = sm + (SM_SMALL >> 2);
    float* b2s = b1s + 128;
    float* w3s = b2s + 64;
    float* b3s = w3s + 64;

    if (tid < 128) b1s[tid] = b1[tid];
    if (tid < 64) { b2s[tid] = b2[tid]; w3s[tid] = W3[tid]; }
    if (tid == 0)  b3s[0] = b3[0];

    // ---- per-thread edge index (thread owns edge le; h: 0=src 1=dst) ----
    const int le = tid >> 1, h = tid & 1;
    const long long eg = (long long)tile_base + le;
    int gidx = 0;
    {
        const unsigned* p = (const unsigned*)eiv;
        unsigned orv = 0;
        #pragma unroll
        for (int i = 0; i < 16; i++) orv |= p[2 * i + 1];
        if (eg < n_edges) {
            if (orv == 0) {   // int64 indices
                const long long* e64 = (const long long*)eiv;
                gidx = (int)(h ? e64[(long long)n_edges + eg] : e64[eg]);
            } else {
                const int* e32 = (const int*)eiv;
                gidx = h ? e32[n_edges + eg] : e32[eg];
            }
        }
    }

    // ---- prologue: staging(0) ----
    stage_panel(sbase, z, 0, gidx, le, h); CP_COMMIT();

    float c1[2][8][4];
    #pragma unroll
    for (int mt = 0; mt < 2; mt++)
        #pragma unroll
        for (int nt = 0; nt < 8; nt++)
            #pragma unroll
            for (int v = 0; v < 4; v++) c1[mt][nt][v] = 0.f;

    const uint32_t* Fs = (const uint32_t*)(smem + SM_FEAT);
    const int brow = tid & 127, bh = tid >> 7;   // conflict-free build mapping

    // =============== layer 1: 4 j-panels x 4 feature chunks =================
    #pragma unroll 1
    for (int j = 0; j < 4; j++) {
        CP_WAIT0();                        // staging(j) landed (this thread)
        __syncthreads();                   // all slices landed; prev chunk reads done

        stage_B4(sbase, j, tid); CP_COMMIT();   // B(j) x4 in flight (hides under build)

        // ---- build 4 fp16 feature panels from fp32 staging ----
        {
            const float4* Sr = (const float4*)(smem + SM_STG + brow * (STG_STR * 4) + bh * 64);
            const float4* Dr = (const float4*)(smem + SM_STG + 128 * STG_STR * 4 + brow * (STG_STR * 4) + bh * 64);
            uint32_t us[8], ud[8], up[8], uq[8];
            #pragma unroll
            for (int i = 0; i < 4; i++) {
                float4 s4 = Sr[i], d4 = Dr[i];
                __half2 t;
                t = __floats2half2_rn(s4.x, s4.y);                         us[2*i]   = *(uint32_t*)&t;
                t = __floats2half2_rn(s4.z, s4.w);                         us[2*i+1] = *(uint32_t*)&t;
                t = __floats2half2_rn(d4.x, d4.y);                         ud[2*i]   = *(uint32_t*)&t;
                t = __floats2half2_rn(d4.z, d4.w);                         ud[2*i+1] = *(uint32_t*)&t;
                t = __floats2half2_rn(s4.x*d4.x, s4.y*d4.y);               up[2*i]   = *(uint32_t*)&t;
                t = __floats2half2_rn(s4.z*d4.z, s4.w*d4.w);               up[2*i+1] = *(uint32_t*)&t;
                t = __floats2half2_rn(fabsf(s4.x-d4.x), fabsf(s4.y-d4.y)); uq[2*i]   = *(uint32_t*)&t;
                t = __floats2half2_rn(fabsf(s4.z-d4.z), fabsf(s4.w-d4.w)); uq[2*i+1] = *(uint32_t*)&t;
            }
            uint32_t* F0 = (uint32_t*)(smem + SM_FEAT) + brow * FEAT_RSTR + bh * 8;
            #pragma unroll
            for (int pnl = 0; pnl < 4; pnl++) {
                const uint32_t* src = (pnl == 0) ? us : (pnl == 1) ? ud : (pnl == 2) ? up : uq;
                uint32_t* Fp = F0 + pnl * (FEAT_PAN >> 2);
                *(uint4*)(Fp)     = make_uint4(src[0], src[1], src[2], src[3]);
                *(uint4*)(Fp + 4) = make_uint4(src[4], src[5], src[6], src[7]);
            }
        }

        CP_WAIT0();                        // B(j) landed (this thread)
        __syncthreads();                   // features + all B slices visible

        if (j < 3) { stage_panel(sbase, z, j + 1, gidx, le, h); CP_COMMIT(); }

        // ---- 4 chunks, no barriers ----
        #pragma unroll
        for (int fb = 0; fb < 4; fb++)
            l1_chunk(Fs + fb * (FEAT_PAN >> 2), smem + SM_B1 + fb * B1_CH,
                     c1, mi, ni, t4, cl);
    }

    __syncthreads();                       // all FEAT/B reads done
    stage_W2h(sbase, tid); CP_COMMIT();    // into FEAT region; hides under epilogue

    // ---- epilogue 1: A2h = fp16(relu(C1 + b1)) into STG region (dead) ----
    {
        uint32_t* A2 = (uint32_t*)smem;    // half2 granules, row stride A2_RSTR
        #pragma unroll
        for (int mt = 0; mt < 2; mt++) {
            const int r0 = mi * 32 + mt * 16 + t4;
            #pragma unroll
            for (int nt = 0; nt < 8; nt++) {
                const int n0 = ni * 64 + nt * 8 + 2 * cl;
                const int w0 = ni * 32 + nt * 4 + cl;     // half2 word index (n0/2)
                __half2 v0 = __floats2half2_rn(fmaxf(c1[mt][nt][0] + b1s[n0],     0.f),
                                               fmaxf(c1[mt][nt][1] + b1s[n0 + 1], 0.f));
                __half2 v1 = __floats2half2_rn(fmaxf(c1[mt][nt][2] + b1s[n0],     0.f),
                                               fmaxf(c1[mt][nt][3] + b1s[n0 + 1], 0.f));
                A2[r0 * A2_RSTR + w0]       = *(uint32_t*)&v0;
                A2[(r0 + 8) * A2_RSTR + w0] = *(uint32_t*)&v1;
            }
        }
    }
    CP_WAIT0();          // W2h landed (this thread)
    __syncthreads();     // A2h + W2h visible to all

    // =============== layer 2: fp16, K=128 (8 k-steps), N=64 =================
    float c2[2][4][4];
    #pragma unroll
    for (int mt = 0; mt < 2; mt++)
        #pragma unroll
        for (int nt = 0; nt < 4; nt++)
            #pragma unroll
            for (int v = 0; v < 4; v++) c2[mt][nt][v] = 0.f;

    {
        const uint32_t* A2 = (const uint32_t*)smem;
        #pragma unroll
        for (int ks = 0; ks < 8; ks++) {
            uint32_t a[2][4];
            #pragma unroll
            for (int mt = 0; mt < 2; mt++) {
                const int g0 = (mi * 32 + mt * 16 + t4) * A2_RSTR + cl + 8 * ks;
                a[mt][0] = A2[g0];
                a[mt][1] = A2[g0 + 8 * A2_RSTR];
                a[mt][2] = A2[g0 + 4];
                a[mt][3] = A2[g0 + 4 + 8 * A2_RSTR];
            }
            uint32_t b[4][2];
            #pragma unroll
            for (int np = 0; np < 2; np++) {
                const int q = ni * 16 + np * 8 + t4;
                const char* bp = smem + SM_W2H + ((8 * ks + cl) * W2_STR + q * 2) * 4;
                uint2 p0 = *(const uint2*)bp;
                uint2 p1 = *(const uint2*)(bp + 4 * W2_STR * 4);
                b[np][0]     = p0.x;  b[np + 2][0] = p0.y;
                b[np][1]     = p1.x;  b[np + 2][1] = p1.y;
            }
            #pragma unroll
            for (int mt = 0; mt < 2; mt++)
                #pragma unroll
                for (int nt = 0; nt < 4; nt++)
                    MMA16(c2[mt][nt], a[mt], b[nt]);
        }
    }

    // =============== layer 3: relu(C2+b2) . W3 + b3 =========================
    float* R = sm + (SM_R >> 2);
    #pragma unroll
    for (int mt = 0; mt < 2; mt++) {
        float p0 = 0.f, p1 = 0.f;
        #pragma unroll
        for (int nt = 0; nt < 4; nt++) {
            const int n0 = ni * 32 + nt * 8 + 2 * cl;
            const float w0 = w3s[n0], w1 = w3s[n0 + 1];
            const float g0 = b2s[n0], g1 = b2s[n0 + 1];
            p0 += fmaxf(c2[mt][nt][0] + g0, 0.f) * w0 + fmaxf(c2[mt][nt][1] + g1, 0.f) * w1;
            p1 += fmaxf(c2[mt][nt][2] + g0, 0.f) * w0 + fmaxf(c2[mt][nt][3] + g1, 0.f) * w1;
        }
        p0 += __shfl_xor_sync(0xffffffffu, p0, 1);
        p0 += __shfl_xor_sync(0xffffffffu, p0, 2);
        p1 += __shfl_xor_sync(0xffffffffu, p1, 1);
        p1 += __shfl_xor_sync(0xffffffffu, p1, 2);
        if (cl == 0) {
            const int r0 = mi * 32 + mt * 16 + t4;
            R[ni * 128 + r0]     = p0;
            R[ni * 128 + r0 + 8] = p1;
        }
    }
    __syncthreads();
    if (tid < 128) {
        const long long e = (long long)tile_base + tid;
        if (e < n_edges) out[e] = R[tid] + R[128 + tid] + b3s[0];
    }
}

// ---------------------------------------------------------------------------
extern "C" void kernel_launch(void* const* d_in, const int* in_sizes, int n_in,
                              void* d_out, int out_size) {
    const float* z  = (const float*)d_in[0];
    const void*  ei = (const void*) d_in[1];
    const float* W1 = (const float*)d_in[2];
    const float* b1 = (const float*)d_in[3];
    const float* W2 = (const float*)d_in[4];
    const float* b2 = (const float*)d_in[5];
    const float* W3 = (const float*)d_in[6];
    const float* b3 = (const float*)d_in[7];
    const int n = out_size;

    prep_weights<<<(256 * 64 + 64 * 32 + 255) / 256, 256>>>(W1, W2);

    cudaFuncSetAttribute(lp_main, cudaFuncAttributeMaxDynamicSharedMemorySize, SMEM_TOTAL);
    lp_main<<<(n + TE - 1) / TE, 256, SMEM_TOTAL>>>(z, ei, b1, b2, W3, b3, (float*)d_out, n);
}

// round 9
// speedup vs baseline: 3.1493x; 1.0645x over previous
#include <cuda_runtime.h>
#include <cuda_fp16.h>
#include <cstdint>

// ============================================================================
// LinkPredictor, sm_103 (no tcgen05). All-fp16 mma.sync m16n8k16 (fp32 accum).
// R9: FEAT smem panels eliminated — feature fragments (s, d, s*d, |s-d|) are
// built in registers from fp32 staging at MMA time (one LDS.64 pair per
// source position, features rounded once from fp32 math — precision model
// unchanged). Freed smem funds double-buffered staging (gather overlap);
// B chunks single-buffered (L2-resident, covered by ks=0 feature build).
//   layer1: A[128,512] feat @ W1 -> c1 ; layer2 fp16: relu(c1+b1) @ W2 -> c2 ;
//   layer3: relu(c2+b2).W3+b3 -> out.
// ============================================================================

#define TE 128

// prep scratch (fp16 pair-interleaved weights)
__device__ __align__(16) uint2 g_W1h[256 * 64];  // [kp][q]: half2{W1[2kp][n],W1[2kp+1][n]}, n=(q&31)+(q>>5)*64
__device__ __align__(16) uint2 g_W2h[64 * 32];   // [kp][q]: half2{W2[2kp][n],W2[2kp+1][n]}, n=(q&15)+(q>>4)*32

// ---- smem geometry ----
// staging row (one edge): s[32]f32 | d[32]f32 | pad -> 72 words (72 mod 32 = 8:
// LDS.64 source loads conflict-free per half-warp phase: banks 8*t4+2*cl distinct)
#define STG_STR   72
#define STG_BUF   36864               // 128 rows x 288 B
#define SM_STG    0                   // 2 buffers = 73728 B
#define SM_B1     73728               // 4 chunk buffers x 16 kp-rows x 544B = 34816 B
#define B1_CH     8704
#define B1_STR    136                 // words per kp row; 136 mod 32 = 8
#define SM_SMALL  108544              // b1[128]|b2[64]|w3[64]|b3
#define SMEM_TOTAL 109600
// phase 2 overlays (staging buf0 dead after chunks(2); buf1 + B dead after
// post-chunks sync):
#define SM_A2H    0                   // fp16 [128][68w] = 34816 B (buf0 region)
#define A2_RSTR   68                  // 68 mod 32 = 4 -> L2 A-frag LDS.32 conflict-free
#define SM_W2H    36864               // 64 kp x 72w = 18432 B (buf1 region)
#define W2_STR    72
#define SM_R      73728               // [2][128] f32 (B region)

__device__ __forceinline__ uint32_t smem_u32(const void* p) {
    uint32_t a;
    asm("{ .reg .u64 t; cvta.to.shared.u64 t, %1; cvt.u32.u64 %0, t; }" : "=r"(a) : "l"(p));
    return a;
}
__device__ __forceinline__ void cp16(uint32_t d, const void* s) {
    asm volatile("cp.async.ca.shared.global [%0], [%1], 16;" :: "r"(d), "l"(s) : "memory");
}
#define CP_COMMIT() asm volatile("cp.async.commit_group;" ::: "memory")
#define CP_WAIT0()  asm volatile("cp.async.wait_group 0;"  ::: "memory")
#define CP_WAIT1()  asm volatile("cp.async.wait_group 1;"  ::: "memory")

// fp16 m16n8k16, fp32 accum
#define MMA16(c, a, b)                                                          \
    asm volatile("mma.sync.aligned.m16n8k16.row.col.f32.f16.f16.f32 "           \
                 "{%0,%1,%2,%3}, {%4,%5,%6,%7}, {%8,%9}, {%0,%1,%2,%3};"        \
                 : "+f"((c)[0]), "+f"((c)[1]), "+f"((c)[2]), "+f"((c)[3])       \
                 : "r"((a)[0]), "r"((a)[1]), "r"((a)[2]), "r"((a)[3]),          \
                   "r"((b)[0]), "r"((b)[1]))

// ---------------------------------------------------------------------------
__global__ void prep_weights(const float* __restrict__ W1, const float* __restrict__ W2) {
    int i = blockIdx.x * blockDim.x + threadIdx.x;
    if (i < 256 * 64) {
        int kp = i >> 6, q = i & 63;
        int n = (q & 31) + ((q >> 5) << 6);
        uint2 v;
        __half2 lo = __floats2half2_rn(W1[(2*kp) * 128 + n],      W1[(2*kp+1) * 128 + n]);
        __half2 hi = __floats2half2_rn(W1[(2*kp) * 128 + n + 32], W1[(2*kp+1) * 128 + n + 32]);
        v.x = *(uint32_t*)&lo;  v.y = *(uint32_t*)&hi;
        g_W1h[i] = v;
    } else {
        int j = i - 256 * 64;
        if (j < 64 * 32) {
            int kp = j >> 5, q = j & 31;
            int n = (q & 15) + ((q >> 4) << 5);
            uint2 v;
            __half2 lo = __floats2half2_rn(W2[(2*kp) * 64 + n],      W2[(2*kp+1) * 64 + n]);
            __half2 hi = __floats2half2_rn(W2[(2*kp) * 64 + n + 16], W2[(2*kp+1) * 64 + n + 16]);
            v.x = *(uint32_t*)&lo;  v.y = *(uint32_t*)&hi;
            g_W2h[j] = v;
        }
    }
}

// ---------------------------------------------------------------------------
// build all 4 fp16 feature fragment sets for one k-step (K=16) from staging
// ---------------------------------------------------------------------------
__device__ __forceinline__ void build_feats(const float* __restrict__ stg, int ks,
                                            int mi, int t4, int cl,
                                            uint32_t (&fS)[2][4], uint32_t (&fD)[2][4],
                                            uint32_t (&fP)[2][4], uint32_t (&fQ)[2][4])
{
    #pragma unroll
    for (int mt = 0; mt < 2; mt++) {
        const float* base = stg + (mi * 32 + mt * 16 + t4) * STG_STR + 16 * ks + 2 * cl;
        #pragma unroll
        for (int pp = 0; pp < 4; pp++) {
            // a-reg pp: row offset 8*(pp&1), k offset 8*(pp>>1)
            const float* p = base + (pp & 1) * (8 * STG_STR) + (pp >> 1) * 8;
            float2 sv = *(const float2*)p;
            float2 dv = *(const float2*)(p + 32);
            __half2 t;
            t = __floats2half2_rn(sv.x, sv.y);                         fS[mt][pp] = *(uint32_t*)&t;
            t = __floats2half2_rn(dv.x, dv.y);                         fD[mt][pp] = *(uint32_t*)&t;
            t = __floats2half2_rn(sv.x * dv.x, sv.y * dv.y);           fP[mt][pp] = *(uint32_t*)&t;
            t = __floats2half2_rn(fabsf(sv.x - dv.x), fabsf(sv.y - dv.y)); fQ[mt][pp] = *(uint32_t*)&t;
        }
    }
}

// 4 feature chunks of one k-step: B loads + 16 MMAs each
__device__ __forceinline__ void mma_ks(const char* __restrict__ smem, int ks,
                                       int ni, int t4, int cl,
                                       const uint32_t (&fS)[2][4], const uint32_t (&fD)[2][4],
                                       const uint32_t (&fP)[2][4], const uint32_t (&fQ)[2][4],
                                       float (&c1)[2][8][4])
{
    #pragma unroll
    for (int fb = 0; fb < 4; fb++) {
        const char* Bb = smem + SM_B1 + fb * B1_CH + (8 * ks + cl) * (B1_STR * 4);
        uint32_t b[8][2];
        #pragma unroll
        for (int np = 0; np < 4; np++) {
            const int q = ni * 32 + np * 8 + t4;
            uint2 p0 = *(const uint2*)(Bb + q * 8);
            uint2 p1 = *(const uint2*)(Bb + 4 * (B1_STR * 4) + q * 8);
            b[np][0]     = p0.x;  b[np + 4][0] = p0.y;
            b[np][1]     = p1.x;  b[np + 4][1] = p1.y;
        }
        const uint32_t (*fA)[4] = (fb == 0) ? fS : (fb == 1) ? fD : (fb == 2) ? fP : fQ;
        #pragma unroll
        for (int mt = 0; mt < 2; mt++)
            #pragma unroll
            for (int nt = 0; nt < 8; nt++)
                MMA16(c1[mt][nt], fA[mt], b[nt]);
    }
}

// stage ALL 4 fp16 B chunks of panel j (chunk fb -> kp base fb*64+j*16)
__device__ __forceinline__ void stage_B4(uint32_t sbase, int j, int tid) {
    #pragma unroll
    for (int fb = 0; fb < 4; fb++) {
        const int kc = (fb << 6) + (j << 4);
        #pragma unroll
        for (int r = 0; r < 2; r++) {
            int q = tid + 256 * r;
            int row = q >> 5, seg = q & 31;
            cp16(sbase + SM_B1 + fb * B1_CH + row * (B1_STR * 4) + seg * 16,
                 (const char*)(g_W1h + (kc + row) * 64) + seg * 16);
        }
    }
}

// stage this thread's 128B z-slice into staging buffer buf (row le, half h)
__device__ __forceinline__ void stage_panel(uint32_t sbase, const float* __restrict__ z,
                                            int buf, int j, int gidx, int le, int h) {
    uint32_t dst = sbase + SM_STG + (uint32_t)buf * STG_BUF
                 + (uint32_t)le * (STG_STR * 4) + (uint32_t)h * 128;
    const float* src = z + (long long)gidx * 128 + j * 32;
    #pragma unroll
    for (int s = 0; s < 8; s++) cp16(dst + s * 16, src + s * 4);
}

// stage W2h (64 kp rows x 256B) into buf1 region
__device__ __forceinline__ void stage_W2h(uint32_t sbase, int tid) {
    #pragma unroll
    for (int r = 0; r < 4; r++) {
        int i = tid + 256 * r;
        int row = i >> 4, seg = i & 15;
        cp16(sbase + SM_W2H + row * (W2_STR * 4) + seg * 16,
             (const char*)(g_W2h + row * 32) + seg * 16);
    }
}

// ---------------------------------------------------------------------------
__global__ void __launch_bounds__(256, 2)
lp_main(const float* __restrict__ z,
        const void*  __restrict__ eiv,
        const float* __restrict__ b1,
        const float* __restrict__ b2,
        const float* __restrict__ W3,
        const float* __restrict__ b3,
        float* __restrict__ out,
        int n_edges)
{
    extern __shared__ char smem[];
    float* sm = (float*)smem;
    const uint32_t sbase = smem_u32(smem);
    const int tid  = threadIdx.x;
    const int lane = tid & 31;
    const int wid  = tid >> 5;
    const int mi   = wid >> 1;
    const int ni   = wid & 1;
    const int t4   = lane >> 2;
    const int cl   = lane & 3;
    const int tile_base = blockIdx.x * TE;

    float* b1s = sm + (SM_SMALL >> 2);
    float* b2s = b1s + 128;
    float* w3s = b2s + 64;
    float* b3s = w3s + 64;

    if (tid < 128) b1s[tid] = b1[tid];
    if (tid < 64) { b2s[tid] = b2[tid]; w3s[tid] = W3[tid]; }
    if (tid == 0)  b3s[0] = b3[0];

    // ---- per-thread edge index (thread owns edge le; h: 0=src 1=dst) ----
    const int le = tid >> 1, h = tid & 1;
    const long long eg = (long long)tile_base + le;
    int gidx = 0;
    {
        const unsigned* p = (const unsigned*)eiv;
        unsigned orv = 0;
        #pragma unroll
        for (int i = 0; i < 16; i++) orv |= p[2 * i + 1];
        if (eg < n_edges) {
            if (orv == 0) {   // int64 indices
                const long long* e64 = (const long long*)eiv;
                gidx = (int)(h ? e64[(long long)n_edges + eg] : e64[eg]);
            } else {
                const int* e32 = (const int*)eiv;
                gidx = h ? e32[n_edges + eg] : e32[eg];
            }
        }
    }

    // ---- prologue: staging(0) into buf0 ----
    stage_panel(sbase, z, 0, 0, gidx, le, h); CP_COMMIT();

    float c1[2][8][4];
    #pragma unroll
    for (int mt = 0; mt < 2; mt++)
        #pragma unroll
        for (int nt = 0; nt < 8; nt++)
            #pragma unroll
            for (int v = 0; v < 4; v++) c1[mt][nt][v] = 0.f;

    // =============== layer 1: 4 j-panels x (2 ks x 4 fb) ====================
    #pragma unroll 1
    for (int j = 0; j < 4; j++) {
        CP_WAIT0();                        // staging(j) landed (this thread)
        __syncthreads();                   // all slices visible; prev reads done

        stage_B4(sbase, j, tid); CP_COMMIT();              // group B(j)
        if (j < 3) stage_panel(sbase, z, (j + 1) & 1, j + 1, gidx, le, h);
        CP_COMMIT();                                       // group S (empty at j=3)

        const float* stg = (const float*)(smem + SM_STG + (j & 1) * STG_BUF);

        uint32_t fS[2][4], fD[2][4], fP[2][4], fQ[2][4];
        build_feats(stg, 0, mi, t4, cl, fS, fD, fP, fQ);   // covers B L2 latency

        CP_WAIT1();                        // B(j) landed (this thread), S may fly
        __syncthreads();                   // all B slices visible

        mma_ks(smem, 0, ni, t4, cl, fS, fD, fP, fQ, c1);
        build_feats(stg, 1, mi, t4, cl, fS, fD, fP, fQ);
        mma_ks(smem, 1, ni, t4, cl, fS, fD, fP, fQ, c1);
    }

    __syncthreads();                       // all staging/B reads done
    stage_W2h(sbase, tid); CP_COMMIT();    // into buf1 region; hides under epilogue

    // ---- epilogue 1: A2h = fp16(relu(C1 + b1)) into buf0 region ----
    {
        uint32_t* A2 = (uint32_t*)smem;    // half2 granules, row stride A2_RSTR
        #pragma unroll
        for (int mt = 0; mt < 2; mt++) {
            const int r0 = mi * 32 + mt * 16 + t4;
            #pragma unroll
            for (int nt = 0; nt < 8; nt++) {
                const int n0 = ni * 64 + nt * 8 + 2 * cl;
                const int w0 = ni * 32 + nt * 4 + cl;     // half2 word index (n0/2)
                __half2 v0 = __floats2half2_rn(fmaxf(c1[mt][nt][0] + b1s[n0],     0.f),
                                               fmaxf(c1[mt][nt][1] + b1s[n0 + 1], 0.f));
                __half2 v1 = __floats2half2_rn(fmaxf(c1[mt][nt][2] + b1s[n0],     0.f),
                                               fmaxf(c1[mt][nt][3] + b1s[n0 + 1], 0.f));
                A2[r0 * A2_RSTR + w0]       = *(uint32_t*)&v0;
                A2[(r0 + 8) * A2_RSTR + w0] = *(uint32_t*)&v1;
            }
        }
    }
    CP_WAIT0();          // W2h landed (this thread)
    __syncthreads();     // A2h + W2h visible to all

    // =============== layer 2: fp16, K=128 (8 k-steps), N=64 =================
    float c2[2][4][4];
    #pragma unroll
    for (int mt = 0; mt < 2; mt++)
        #pragma unroll
        for (int nt = 0; nt < 4; nt++)
            #pragma unroll
            for (int v = 0; v < 4; v++) c2[mt][nt][v] = 0.f;

    {
        const uint32_t* A2 = (const uint32_t*)smem;
        #pragma unroll
        for (int ks = 0; ks < 8; ks++) {
            uint32_t a[2][4];
            #pragma unroll
            for (int mt = 0; mt < 2; mt++) {
                const int g0 = (mi * 32 + mt * 16 + t4) * A2_RSTR + cl + 8 * ks;
                a[mt][0] = A2[g0];
                a[mt][1] = A2[g0 + 8 * A2_RSTR];
                a[mt][2] = A2[g0 + 4];
                a[mt][3] = A2[g0 + 4 + 8 * A2_RSTR];
            }
            uint32_t b[4][2];
            #pragma unroll
            for (int np = 0; np < 2; np++) {
                const int q = ni * 16 + np * 8 + t4;
                const char* bp = smem + SM_W2H + ((8 * ks + cl) * W2_STR + q * 2) * 4;
                uint2 p0 = *(const uint2*)bp;
                uint2 p1 = *(const uint2*)(bp + 4 * W2_STR * 4);
                b[np][0]     = p0.x;  b[np + 2][0] = p0.y;
                b[np][1]     = p1.x;  b[np + 2][1] = p1.y;
            }
            #pragma unroll
            for (int mt = 0; mt < 2; mt++)
                #pragma unroll
                for (int nt = 0; nt < 4; nt++)
                    MMA16(c2[mt][nt], a[mt], b[nt]);
        }
    }

    // =============== layer 3: relu(C2+b2) . W3 + b3 =========================
    float* R = sm + (SM_R >> 2);
    #pragma unroll
    for (int mt = 0; mt < 2; mt++) {
        float p0 = 0.f, p1 = 0.f;
        #pragma unroll
        for (int nt = 0; nt < 4; nt++) {
            const int n0 = ni * 32 + nt * 8 + 2 * cl;
            const float w0 = w3s[n0], w1 = w3s[n0 + 1];
            const float g0 = b2s[n0], g1 = b2s[n0 + 1];
            p0 += fmaxf(c2[mt][nt][0] + g0, 0.f) * w0 + fmaxf(c2[mt][nt][1] + g1, 0.f) * w1;
            p1 += fmaxf(c2[mt][nt][2] + g0, 0.f) * w0 + fmaxf(c2[mt][nt][3] + g1, 0.f) * w1;
        }
        p0 += __shfl_xor_sync(0xffffffffu, p0, 1);
        p0 += __shfl_xor_sync(0xffffffffu, p0, 2);
        p1 += __shfl_xor_sync(0xffffffffu, p1, 1);
        p1 += __shfl_xor_sync(0xffffffffu, p1, 2);
        if (cl == 0) {
            const int r0 = mi * 32 + mt * 16 + t4;
            R[ni * 128 + r0]     = p0;
            R[ni * 128 + r0 + 8] = p1;
        }
    }
    __syncthreads();
    if (tid < 128) {
        const long long e = (long long)tile_base + tid;
        if (e < n_edges) out[e] = R[tid] + R[128 + tid] + b3s[0];
    }
}

// ---------------------------------------------------------------------------
extern "C" void kernel_launch(void* const* d_in, const int* in_sizes, int n_in,
                              void* d_out, int out_size) {
    const float* z  = (const float*)d_in[0];
    const void*  ei = (const void*) d_in[1];
    const float* W1 = (const float*)d_in[2];
    const float* b1 = (const float*)d_in[3];
    const float* W2 = (const float*)d_in[4];
    const float* b2 = (const float*)d_in[5];
    const float* W3 = (const float*)d_in[6];
    const float* b3 = (const float*)d_in[7];
    const int n = out_size;

    prep_weights<<<(256 * 64 + 64 * 32 + 255) / 256, 256>>>(W1, W2);

    cudaFuncSetAttribute(lp_main, cudaFuncAttributeMaxDynamicSharedMemorySize, SMEM_TOTAL);
    lp_main<<<(n + TE - 1) / TE, 256, SMEM_TOTAL>>>(z, ei, b1, b2, W3, b3, (float*)d_out, n);
}

// round 14
// speedup vs baseline: 3.4219x; 1.0866x over previous
#include <cuda_runtime.h>
#include <cuda_fp16.h>
#include <cstdint>

// ============================================================================
// LinkPredictor, sm_103 (no tcgen05). All-fp16 mma.sync m16n8k16 (fp32 accum).
// R10: big-tile regime — TE=256 edges/CTA, 1 CTA/SM (255 regs), 8 warps of
// 64-row x 64-col tiles (c1[4][8][4]=128 accums). Halves per-edge B-fragment
// bytes (4 -> 2 KB/edge); total L1 bytes/edge -29%. Feature fragments still
// built in registers from fp32 staging (precision model unchanged).
//   layer1: A[256,512] feat @ W1 -> c1 ; layer2 fp16: relu(c1+b1) @ W2 -> c2 ;
//   layer3: relu(c2+b2).W3+b3 -> out.
// ============================================================================

#define TE 256

// prep scratch (fp16 pair-interleaved weights)
__device__ __align__(16) uint2 g_W1h[256 * 64];  // [kp][q]: half2{W1[2kp][n],W1[2kp+1][n]}, n=(q&31)+(q>>5)*64
__device__ __align__(16) uint2 g_W2h[64 * 32];   // [kp][q]: half2{W2[2kp][n],W2[2kp+1][n]}, n=(q&15)+(q>>4)*32

// ---- smem geometry ----
// staging row (one edge): s[32]f32 | d[32]f32 | 8 pad words = 72 words (288B)
// 72 mod 32 = 8 -> LDS.64 source reads conflict-free per phase (banks 8t4+2cl)
#define STG_STR   72
#define STG_BUF   73728               // 256 rows x 288 B
#define SM_STG    0                   // 2 buffers = 147456 B
#define SM_B1     147456              // 4 chunk buffers x 16 kp-rows x 544B = 34816 B
#define B1_CH     8704
#define B1_STR    136                 // words per kp row; 136 mod 32 = 8
#define SM_SMALL  182272              // b1[128]|b2[64]|w3[64]|b3
#define SMEM_TOTAL 183328
// phase 2 overlays (buf0 dead after j=2 reads drain at j=3 entry; buf1 + B
// dead after post-loop sync):
#define SM_A2H    0                   // fp16 [256][68w] = 69632 B (buf0 region)
#define A2_RSTR   68                  // 68 mod 32 = 4 -> conflict-free frags
#define SM_W2H    73728               // 64 kp x 72w = 18432 B (buf1 region)
#define W2_STR    72
#define SM_R      147456              // [2][256] f32 = 2048 B (B region)

__device__ __forceinline__ uint32_t smem_u32(const void* p) {
    uint32_t a;
    asm("{ .reg .u64 t; cvta.to.shared.u64 t, %1; cvt.u32.u64 %0, t; }" : "=r"(a) : "l"(p));
    return a;
}
__device__ __forceinline__ void cp16(uint32_t d, const void* s) {
    asm volatile("cp.async.ca.shared.global [%0], [%1], 16;" :: "r"(d), "l"(s) : "memory");
}
__device__ __forceinline__ void cp16cg(uint32_t d, const void* s) {   // L1-bypass (no-reuse gather)
    asm volatile("cp.async.cg.shared.global [%0], [%1], 16;" :: "r"(d), "l"(s) : "memory");
}
#define CP_COMMIT() asm volatile("cp.async.commit_group;" ::: "memory")
#define CP_WAIT0()  asm volatile("cp.async.wait_group 0;"  ::: "memory")
#define CP_WAIT1()  asm volatile("cp.async.wait_group 1;"  ::: "memory")

// fp16 m16n8k16, fp32 accum
#define MMA16(c, a, b)                                                          \
    asm volatile("mma.sync.aligned.m16n8k16.row.col.f32.f16.f16.f32 "           \
                 "{%0,%1,%2,%3}, {%4,%5,%6,%7}, {%8,%9}, {%0,%1,%2,%3};"        \
                 : "+f"((c)[0]), "+f"((c)[1]), "+f"((c)[2]), "+f"((c)[3])       \
                 : "r"((a)[0]), "r"((a)[1]), "r"((a)[2]), "r"((a)[3]),          \
                   "r"((b)[0]), "r"((b)[1]))

// ---------------------------------------------------------------------------
__global__ void prep_weights(const float* __restrict__ W1, const float* __restrict__ W2) {
    int i = blockIdx.x * blockDim.x + threadIdx.x;
    if (i < 256 * 64) {
        int kp = i >> 6, q = i & 63;
        int n = (q & 31) + ((q >> 5) << 6);
        uint2 v;
        __half2 lo = __floats2half2_rn(W1[(2*kp) * 128 + n],      W1[(2*kp+1) * 128 + n]);
        __half2 hi = __floats2half2_rn(W1[(2*kp) * 128 + n + 32], W1[(2*kp+1) * 128 + n + 32]);
        v.x = *(uint32_t*)&lo;  v.y = *(uint32_t*)&hi;
        g_W1h[i] = v;
    } else {
        int j = i - 256 * 64;
        if (j < 64 * 32) {
            int kp = j >> 5, q = j & 31;
            int n = (q & 15) + ((q >> 4) << 5);
            uint2 v;
            __half2 lo = __floats2half2_rn(W2[(2*kp) * 64 + n],      W2[(2*kp+1) * 64 + n]);
            __half2 hi = __floats2half2_rn(W2[(2*kp) * 64 + n + 16], W2[(2*kp+1) * 64 + n + 16]);
            v.x = *(uint32_t*)&lo;  v.y = *(uint32_t*)&hi;
            g_W2h[j] = v;
        }
    }
}

// ---------------------------------------------------------------------------
// build all 4 fp16 feature fragment sets for one k-step (K=16), 4 m-tiles
// ---------------------------------------------------------------------------
__device__ __forceinline__ void build_feats(const float* __restrict__ stg, int ks,
                                            int mi, int t4, int cl,
                                            uint32_t (&fS)[4][4], uint32_t (&fD)[4][4],
                                            uint32_t (&fP)[4][4], uint32_t (&fQ)[4][4])
{
    #pragma unroll
    for (int mt = 0; mt < 4; mt++) {
        const float* base = stg + (mi * 64 + mt * 16 + t4) * STG_STR + 16 * ks + 2 * cl;
        #pragma unroll
        for (int pp = 0; pp < 4; pp++) {
            const float* p = base + (pp & 1) * (8 * STG_STR) + (pp >> 1) * 8;
            float2 sv = *(const float2*)p;
            float2 dv = *(const float2*)(p + 32);
            __half2 t;
            t = __floats2half2_rn(sv.x, sv.y);                             fS[mt][pp] = *(uint32_t*)&t;
            t = __floats2half2_rn(dv.x, dv.y);                             fD[mt][pp] = *(uint32_t*)&t;
            t = __floats2half2_rn(sv.x * dv.x, sv.y * dv.y);               fP[mt][pp] = *(uint32_t*)&t;
            t = __floats2half2_rn(fabsf(sv.x - dv.x), fabsf(sv.y - dv.y)); fQ[mt][pp] = *(uint32_t*)&t;
        }
    }
}

// 4 feature chunks of one k-step: B loads (transient regs) + 32 MMAs each
__device__ __forceinline__ void mma_ks(const char* __restrict__ smem, int ks,
                                       int ni, int t4, int cl,
                                       const uint32_t (&fS)[4][4], const uint32_t (&fD)[4][4],
                                       const uint32_t (&fP)[4][4], const uint32_t (&fQ)[4][4],
                                       float (&c1)[4][8][4])
{
    #pragma unroll
    for (int fb = 0; fb < 4; fb++) {
        const char* Bb = smem + SM_B1 + fb * B1_CH + (8 * ks + cl) * (B1_STR * 4);
        const uint32_t (*fA)[4] = (fb == 0) ? fS : (fb == 1) ? fD : (fb == 2) ? fP : fQ;
        #pragma unroll
        for (int np = 0; np < 4; np++) {
            const int q = ni * 32 + np * 8 + t4;
            uint2 p0 = *(const uint2*)(Bb + q * 8);
            uint2 p1 = *(const uint2*)(Bb + 4 * (B1_STR * 4) + q * 8);
            uint32_t bl[2] = { p0.x, p1.x };
            uint32_t bh[2] = { p0.y, p1.y };
            #pragma unroll
            for (int mt = 0; mt < 4; mt++) {
                MMA16(c1[mt][np],     fA[mt], bl);
                MMA16(c1[mt][np + 4], fA[mt], bh);
            }
        }
    }
}

// stage ALL 4 fp16 B chunks of panel j (chunk fb -> kp base fb*64+j*16)
__device__ __forceinline__ void stage_B4(uint32_t sbase, int j, int tid) {
    #pragma unroll
    for (int fb = 0; fb < 4; fb++) {
        const int kc = (fb << 6) + (j << 4);
        #pragma unroll
        for (int r = 0; r < 2; r++) {
            int q = tid + 256 * r;
            int row = q >> 5, seg = q & 31;
            cp16(sbase + SM_B1 + fb * B1_CH + row * (B1_STR * 4) + seg * 16,
                 (const char*)(g_W1h + (kc + row) * 64) + seg * 16);
        }
    }
}

// stage this thread's edge (both s and d 128B slices) into buffer buf
__device__ __forceinline__ void stage_panel(uint32_t sbase, const float* __restrict__ z,
                                            int buf, int j, int gs, int gd, int le) {
    uint32_t dst = sbase + SM_STG + (uint32_t)buf * STG_BUF + (uint32_t)le * (STG_STR * 4);
    const float* ps = z + (long long)gs * 128 + j * 32;
    const float* pd = z + (long long)gd * 128 + j * 32;
    #pragma unroll
    for (int s = 0; s < 8; s++) cp16cg(dst + s * 16,       ps + s * 4);
    #pragma unroll
    for (int s = 0; s < 8; s++) cp16cg(dst + 128 + s * 16, pd + s * 4);
}

// stage W2h (64 kp rows x 256B) into buf1 region
__device__ __forceinline__ void stage_W2h(uint32_t sbase, int tid) {
    #pragma unroll
    for (int r = 0; r < 4; r++) {
        int i = tid + 256 * r;
        int row = i >> 4, seg = i & 15;
        cp16(sbase + SM_W2H + row * (W2_STR * 4) + seg * 16,
             (const char*)(g_W2h + row * 32) + seg * 16);
    }
}

// ---------------------------------------------------------------------------
__global__ void __launch_bounds__(256, 1)
lp_main(const float* __restrict__ z,
        const void*  __restrict__ eiv,
        const float* __restrict__ b1,
        const float* __restrict__ b2,
        const float* __restrict__ W3,
        const float* __restrict__ b3,
        float* __restrict__ out,
        int n_edges)
{
    extern __shared__ char smem[];
    float* sm = (float*)smem;
    const uint32_t sbase = smem_u32(smem);
    const int tid  = threadIdx.x;
    const int lane = tid & 31;
    const int wid  = tid >> 5;
    const int mi   = wid >> 1;       // 4 m-slabs of 64 rows
    const int ni   = wid & 1;        // 2 n-halves of 64 cols
    const int t4   = lane >> 2;
    const int cl   = lane & 3;
    const int tile_base = blockIdx.x * TE;

    float* b1s = sm + (SM_SMALL >> 2);
    float* b2s = b1s + 128;
    float* w3s = b2s + 64;
    float* b3s = w3s + 64;

    if (tid < 128) b1s[tid] = b1[tid];
    if (tid < 64) { b2s[tid] = b2[tid]; w3s[tid] = W3[tid]; }
    if (tid == 0)  b3s[0] = b3[0];

    // ---- per-thread edge indices (thread owns edge tid: both src and dst) ----
    const long long eg = (long long)tile_base + tid;
    int gs = 0, gd = 0;
    {
        const unsigned* p = (const unsigned*)eiv;
        unsigned orv = 0;
        #pragma unroll
        for (int i = 0; i < 16; i++) orv |= p[2 * i + 1];
        if (eg < n_edges) {
            if (orv == 0) {   // int64 indices
                const long long* e64 = (const long long*)eiv;
                gs = (int)e64[eg];
                gd = (int)e64[(long long)n_edges + eg];
            } else {
                const int* e32 = (const int*)eiv;
                gs = e32[eg];
                gd = e32[n_edges + eg];
            }
        }
    }

    // ---- prologue: staging(0) into buf0 ----
    stage_panel(sbase, z, 0, 0, gs, gd, tid); CP_COMMIT();

    float c1[4][8][4];
    #pragma unroll
    for (int mt = 0; mt < 4; mt++)
        #pragma unroll
        for (int nt = 0; nt < 8; nt++)
            #pragma unroll
            for (int v = 0; v < 4; v++) c1[mt][nt][v] = 0.f;

    // =============== layer 1: 4 j-panels x (2 ks x 4 fb) ====================
    #pragma unroll 1
    for (int j = 0; j < 4; j++) {
        CP_WAIT0();                        // staging(j) landed (this thread)
        __syncthreads();                   // all slices visible; prev reads done

        stage_B4(sbase, j, tid); CP_COMMIT();              // group B(j)
        if (j < 3) stage_panel(sbase, z, (j + 1) & 1, j + 1, gs, gd, tid);
        CP_COMMIT();                                       // group S (empty at j=3)

        const float* stg = (const float*)(smem + SM_STG + (j & 1) * STG_BUF);

        uint32_t fS[4][4], fD[4][4], fP[4][4], fQ[4][4];
        build_feats(stg, 0, mi, t4, cl, fS, fD, fP, fQ);   // covers B L2 latency

        CP_WAIT1();                        // B(j) landed (this thread), S may fly
        __syncthreads();                   // all B slices visible

        mma_ks(smem, 0, ni, t4, cl, fS, fD, fP, fQ, c1);
        build_feats(stg, 1, mi, t4, cl, fS, fD, fP, fQ);
        mma_ks(smem, 1, ni, t4, cl, fS, fD, fP, fQ, c1);
    }

    __syncthreads();                       // all staging/B reads done
    stage_W2h(sbase, tid); CP_COMMIT();    // into buf1 region; hides under epilogue

    // ---- epilogue 1: A2h = fp16(relu(C1 + b1)) into buf0 region ----
    {
        uint32_t* A2 = (uint32_t*)smem;    // half2 granules, row stride A2_RSTR
        #pragma unroll
        for (int mt = 0; mt < 4; mt++) {
            const int r0 = mi * 64 + mt * 16 + t4;
            #pragma unroll
            for (int nt = 0; nt < 8; nt++) {
                const int n0 = ni * 64 + nt * 8 + 2 * cl;
                const int w0 = ni * 32 + nt * 4 + cl;     // half2 word index (n0/2)
                __half2 v0 = __floats2half2_rn(fmaxf(c1[mt][nt][0] + b1s[n0],     0.f),
                                               fmaxf(c1[mt][nt][1] + b1s[n0 + 1], 0.f));
                __half2 v1 = __floats2half2_rn(fmaxf(c1[mt][nt][2] + b1s[n0],     0.f),
                                               fmaxf(c1[mt][nt][3] + b1s[n0 + 1], 0.f));
                A2[r0 * A2_RSTR + w0]       = *(uint32_t*)&v0;
                A2[(r0 + 8) * A2_RSTR + w0] = *(uint32_t*)&v1;
            }
        }
    }
    CP_WAIT0();          // W2h landed (this thread)
    __syncthreads();     // A2h + W2h visible to all

    // =============== layer 2: fp16, K=128 (8 k-steps), N=64 =================
    float c2[4][4][4];
    #pragma unroll
    for (int mt = 0; mt < 4; mt++)
        #pragma unroll
        for (int nt = 0; nt < 4; nt++)
            #pragma unroll
            for (int v = 0; v < 4; v++) c2[mt][nt][v] = 0.f;

    {
        const uint32_t* A2 = (const uint32_t*)smem;
        #pragma unroll
        for (int ks = 0; ks < 8; ks++) {
            uint32_t a[4][4];
            #pragma unroll
            for (int mt = 0; mt < 4; mt++) {
                const int g0 = (mi * 64 + mt * 16 + t4) * A2_RSTR + cl + 8 * ks;
                a[mt][0] = A2[g0];
                a[mt][1] = A2[g0 + 8 * A2_RSTR];
                a[mt][2] = A2[g0 + 4];
                a[mt][3] = A2[g0 + 4 + 8 * A2_RSTR];
            }
            #pragma unroll
            for (int np = 0; np < 2; np++) {
                const int q = ni * 16 + np * 8 + t4;
                const char* bp = smem + SM_W2H + ((8 * ks + cl) * W2_STR + q * 2) * 4;
                uint2 p0 = *(const uint2*)bp;
                uint2 p1 = *(const uint2*)(bp + 4 * W2_STR * 4);
                uint32_t bl[2] = { p0.x, p1.x };
                uint32_t bh[2] = { p0.y, p1.y };
                #pragma unroll
                for (int mt = 0; mt < 4; mt++) {
                    MMA16(c2[mt][np],     a[mt], bl);
                    MMA16(c2[mt][np + 2], a[mt], bh);
                }
            }
        }
    }

    // =============== layer 3: relu(C2+b2) . W3 + b3 =========================
    float* R = sm + (SM_R >> 2);
    #pragma unroll
    for (int mt = 0; mt < 4; mt++) {
        float p0 = 0.f, p1 = 0.f;
        #pragma unroll
        for (int nt = 0; nt < 4; nt++) {
            const int n0 = ni * 32 + nt * 8 + 2 * cl;
            const float w0 = w3s[n0], w1 = w3s[n0 + 1];
            const float g0 = b2s[n0], g1 = b2s[n0 + 1];
            p0 += fmaxf(c2[mt][nt][0] + g0, 0.f) * w0 + fmaxf(c2[mt][nt][1] + g1, 0.f) * w1;
            p1 += fmaxf(c2[mt][nt][2] + g0, 0.f) * w0 + fmaxf(c2[mt][nt][3] + g1, 0.f) * w1;
        }
        p0 += __shfl_xor_sync(0xffffffffu, p0, 1);
        p0 += __shfl_xor_sync(0xffffffffu, p0, 2);
        p1 += __shfl_xor_sync(0xffffffffu, p1, 1);
        p1 += __shfl_xor_sync(0xffffffffu, p1, 2);
        if (cl == 0) {
            const int r0 = mi * 64 + mt * 16 + t4;
            R[ni * 256 + r0]     = p0;
            R[ni * 256 + r0 + 8] = p1;
        }
    }
    __syncthreads();
    {
        const long long e = (long long)tile_base + tid;
        if (e < n_edges) out[e] = R[tid] + R[256 + tid] + b3s[0];
    }
}

// ---------------------------------------------------------------------------
extern "C" void kernel_launch(void* const* d_in, const int* in_sizes, int n_in,
                              void* d_out, int out_size) {
    const float* z  = (const float*)d_in[0];
    const void*  ei = (const void*) d_in[1];
    const float* W1 = (const float*)d_in[2];
    const float* b1 = (const float*)d_in[3];
    const float* W2 = (const float*)d_in[4];
    const float* b2 = (const float*)d_in[5];
    const float* W3 = (const float*)d_in[6];
    const float* b3 = (const float*)d_in[7];
    const int n = out_size;

    prep_weights<<<(256 * 64 + 64 * 32 + 255) / 256, 256>>>(W1, W2);

    cudaFuncSetAttribute(lp_main, cudaFuncAttributeMaxDynamicSharedMemorySize, SMEM_TOTAL);
    lp_main<<<(n + TE - 1) / TE, 256, SMEM_TOTAL>>>(z, ei, b1, b2, W3, b3, (float*)d_out, n);
}